// round 12
// baseline (speedup 1.0000x reference)
#include <cuda_runtime.h>
#include <cuda_bf16.h>
#include <cstdint>
#include <cstddef>

#define D128 128
#define NFEAT 10
#define N_IP 20000
#define N_CONN 100000
#define N_E 200000
#define T_ITERS 3

// ---------------- scratch (static device globals; no allocation) ----------------
__device__ float g_ip[N_IP * D128];
__device__ float g_conn[N_CONN * D128];
__device__ float g_msg_ip[N_IP * 256];      // [XA | YB]
__device__ float g_msg_conn[N_CONN * 256];  // [XB | YA]
__device__ float g_agg_conn[N_CONN * D128];
__device__ float g_agg_ip[N_IP * D128];
__device__ float g_xm_ip[N_IP * 384];
__device__ float g_hm_ip[N_IP * 384];
__device__ float g_xm_c[N_CONN * 384];
__device__ float g_hm_c[N_CONN * 384];
__device__ float g_rc_conn[N_CONN];
__device__ float g_rc_ip[N_IP];
__device__ float g_H1[N_CONN * D128];
__device__ float g_H2[N_CONN * 64];

// bf16 hi/lo split, transposed weights [N][128]
__device__ __nv_bfloat16 g_ipcat_h[256 * 128], g_ipcat_l[256 * 128];    // [XA w | YB w]
__device__ __nv_bfloat16 g_conncat_h[256 * 128], g_conncat_l[256 * 128];// [XB w | YA w]
__device__ __nv_bfloat16 g_gik_h[384 * 128], g_gik_l[384 * 128];
__device__ __nv_bfloat16 g_gir_h[384 * 128], g_gir_l[384 * 128];
__device__ __nv_bfloat16 g_gck_h[384 * 128], g_gck_l[384 * 128];
__device__ __nv_bfloat16 g_gcr_h[384 * 128], g_gcr_l[384 * 128];
__device__ __nv_bfloat16 g_wr1_h[128 * 128], g_wr1_l[128 * 128];
__device__ __nv_bfloat16 g_wr2_h[64 * 128],  g_wr2_l[64 * 128];

// ---------------- helpers ----------------
__device__ __forceinline__ uint32_t smem_u32(const void* p) {
    uint32_t a;
    asm("{ .reg .u64 t; cvta.to.shared.u64 t, %1; cvt.u32.u64 %0, t; }" : "=r"(a) : "l"(p));
    return a;
}
__device__ __forceinline__ void ldsm_x4(uint32_t& r0, uint32_t& r1, uint32_t& r2, uint32_t& r3,
                                        uint32_t addr) {
    asm volatile("ldmatrix.sync.aligned.m8n8.x4.shared.b16 {%0,%1,%2,%3}, [%4];"
                 : "=r"(r0), "=r"(r1), "=r"(r2), "=r"(r3) : "r"(addr));
}
__device__ __forceinline__ void mma16816(float* c, const uint32_t* a, const uint32_t* b) {
    asm volatile(
        "mma.sync.aligned.m16n8k16.row.col.f32.bf16.bf16.f32 "
        "{%0,%1,%2,%3}, {%4,%5,%6,%7}, {%8,%9}, {%0,%1,%2,%3};"
        : "+f"(c[0]), "+f"(c[1]), "+f"(c[2]), "+f"(c[3])
        : "r"(a[0]), "r"(a[1]), "r"(a[2]), "r"(a[3]), "r"(b[0]), "r"(b[1]));
}
__device__ __forceinline__ uint32_t pack_bf2(__nv_bfloat16 a, __nv_bfloat16 b) {
    return ((uint32_t)__bfloat16_as_ushort(b) << 16) | (uint32_t)__bfloat16_as_ushort(a);
}

// ---------------- multi-job HMMA GEMM: blockIdx.z selects (A, B, C, M, bias, rscale) ------
// Body identical to the proven single-pass kernel; only the per-CTA job select is new.
__global__ __launch_bounds__(256) void mma_gemm_z(
    const float* A0, const float* A1, const float* A2, const float* A3,
    const __nv_bfloat16* Bh0, const __nv_bfloat16* Bh1,
    const __nv_bfloat16* Bh2, const __nv_bfloat16* Bh3,
    const __nv_bfloat16* Bl0, const __nv_bfloat16* Bl1,
    const __nv_bfloat16* Bl2, const __nv_bfloat16* Bl3,
    float* C0, float* C1, float* C2, float* C3,
    int M0, int M1, int M2, int M3,
    const float* bias0, const float* bias1, const float* bias2, const float* bias3,
    const float* rs0, const float* rs1, const float* rs2, const float* rs3,
    int ldc, int do_relu)
{
    constexpr int NTILE = 128;
    constexpr int WM = 64;
    constexpr int MT = 4;
    constexpr int A_HI = 0, A_LO = 32768, B_HI = 65536;
    constexpr int B_LO = B_HI + NTILE * 256;

    const int z = blockIdx.z;
    const float* A;
    const __nv_bfloat16 *Bh, *Bl;
    float* C;
    int M;
    const float* bias;
    const float* rscale;
    if (z == 0)      { A = A0; Bh = Bh0; Bl = Bl0; C = C0; M = M0; bias = bias0; rscale = rs0; }
    else if (z == 1) { A = A1; Bh = Bh1; Bl = Bl1; C = C1; M = M1; bias = bias1; rscale = rs1; }
    else if (z == 2) { A = A2; Bh = Bh2; Bl = Bl2; C = C2; M = M2; bias = bias2; rscale = rs2; }
    else             { A = A3; Bh = Bh3; Bl = Bl3; C = C3; M = M3; bias = bias3; rscale = rs3; }

    const int m0 = blockIdx.x * 128;
    if (m0 >= M) return;

    extern __shared__ char smem[];
    const uint32_t sb = smem_u32(smem);
    const int tid = threadIdx.x, wid = tid >> 5, lane = tid & 31;
    const int col0 = blockIdx.y * NTILE;
    const int wm = wid & 1, wn = wid >> 1;

#pragma unroll
    for (int i = 0; i < 8; i++) {
        int idx = tid + i * 256;
        int r = idx >> 4, kc = idx & 15;
        int gr = m0 + r;
        float4 v0 = make_float4(0.f, 0.f, 0.f, 0.f), v1 = v0;
        if (gr < M) {
            const float* ap = A + (size_t)gr * 128 + kc * 8;
            v0 = *(const float4*)ap;
            v1 = *(const float4*)(ap + 4);
            if (rscale) {
                float s = rscale[gr];
                v0.x *= s; v0.y *= s; v0.z *= s; v0.w *= s;
                v1.x *= s; v1.y *= s; v1.z *= s; v1.w *= s;
            }
        }
        float f[8] = {v0.x, v0.y, v0.z, v0.w, v1.x, v1.y, v1.z, v1.w};
        uint32_t hw[4], lw[4];
#pragma unroll
        for (int j = 0; j < 4; j++) {
            __nv_bfloat16 h0 = __float2bfloat16(f[2 * j]);
            __nv_bfloat16 h1 = __float2bfloat16(f[2 * j + 1]);
            __nv_bfloat16 l0 = __float2bfloat16(f[2 * j] - __bfloat162float(h0));
            __nv_bfloat16 l1 = __float2bfloat16(f[2 * j + 1] - __bfloat162float(h1));
            hw[j] = pack_bf2(h0, h1);
            lw[j] = pack_bf2(l0, l1);
        }
        uint32_t sw = (uint32_t)(r * 256 + ((kc ^ (r & 7)) << 4));
        *(uint4*)(smem + A_HI + sw) = make_uint4(hw[0], hw[1], hw[2], hw[3]);
        *(uint4*)(smem + A_LO + sw) = make_uint4(lw[0], lw[1], lw[2], lw[3]);
    }
#pragma unroll
    for (int i = 0; i < NTILE / 16; i++) {
        int idx = tid + i * 256;
        int r = idx >> 4, kc = idx & 15;
        uint32_t sw = (uint32_t)(r * 256 + ((kc ^ (r & 7)) << 4));
        *(uint4*)(smem + B_HI + sw) = ((const uint4*)(Bh + (size_t)(col0 + r) * 128))[kc];
        *(uint4*)(smem + B_LO + sw) = ((const uint4*)(Bl + (size_t)(col0 + r) * 128))[kc];
    }
    __syncthreads();

    float acc[MT][4][4];
#pragma unroll
    for (int mt = 0; mt < MT; mt++)
#pragma unroll
        for (int nt = 0; nt < 4; nt++)
#pragma unroll
            for (int j = 0; j < 4; j++) acc[mt][nt][j] = 0.f;

    const int rA = ((lane >> 3) & 1) * 8 + (lane & 7);
    const int cA = lane >> 4;
    const int rB = ((lane >> 4) << 3) + (lane & 7);
    const int cB = (lane >> 3) & 1;

#pragma unroll
    for (int ks = 0; ks < 8; ks++) {
        const int kc0 = ks * 2;
        uint32_t ah[MT][4], al[MT][4], bh[4][2], bl[4][2];
#pragma unroll
        for (int mt = 0; mt < MT; mt++) {
            int row = wm * WM + mt * 16 + rA;
            uint32_t ad = sb + A_HI + row * 256 + (((kc0 + cA) ^ (row & 7)) << 4);
            ldsm_x4(ah[mt][0], ah[mt][1], ah[mt][2], ah[mt][3], ad);
            ldsm_x4(al[mt][0], al[mt][1], al[mt][2], al[mt][3], ad + (A_LO - A_HI));
        }
#pragma unroll
        for (int p = 0; p < 2; p++) {
            int row = wn * 32 + p * 16 + rB;
            uint32_t bd = sb + B_HI + row * 256 + (((kc0 + cB) ^ (row & 7)) << 4);
            uint32_t r0, r1, r2, r3;
            ldsm_x4(r0, r1, r2, r3, bd);
            bh[p * 2][0] = r0; bh[p * 2][1] = r1; bh[p * 2 + 1][0] = r2; bh[p * 2 + 1][1] = r3;
            ldsm_x4(r0, r1, r2, r3, bd + (B_LO - B_HI));
            bl[p * 2][0] = r0; bl[p * 2][1] = r1; bl[p * 2 + 1][0] = r2; bl[p * 2 + 1][1] = r3;
        }
#pragma unroll
        for (int mt = 0; mt < MT; mt++)
#pragma unroll
            for (int nt = 0; nt < 4; nt++) {
                mma16816(acc[mt][nt], ah[mt], bh[nt]);
                mma16816(acc[mt][nt], ah[mt], bl[nt]);
                mma16816(acc[mt][nt], al[mt], bh[nt]);
            }
    }

    const int rowg = lane >> 2, colg = (lane & 3) * 2;
#pragma unroll
    for (int mt = 0; mt < MT; mt++) {
#pragma unroll
        for (int nt = 0; nt < 4; nt++) {
            int gc = col0 + wn * 32 + nt * 8 + colg;
            float bx = 0.f, by = 0.f;
            if (bias) { bx = __ldg(bias + gc); by = __ldg(bias + gc + 1); }
#pragma unroll
            for (int h = 0; h < 2; h++) {
                int gr = m0 + wm * WM + mt * 16 + h * 8 + rowg;
                if (gr < M) {
                    float x = acc[mt][nt][h * 2 + 0] + bx;
                    float y = acc[mt][nt][h * 2 + 1] + by;
                    if (do_relu) { x = fmaxf(x, 0.f); y = fmaxf(y, 0.f); }
                    float2 o; o.x = x; o.y = y;
                    *(float2*)(C + (size_t)gr * ldc + gc) = o;
                }
            }
        }
    }
}

// ---------------- NTILE=64 GEMM (readout H2 only; unchanged from R5) ----------------
__global__ __launch_bounds__(256) void mma_gemm64(
    const float* __restrict__ A, const __nv_bfloat16* __restrict__ Bh,
    const __nv_bfloat16* __restrict__ Bl, float* __restrict__ C,
    int M, int ldc, const float* __restrict__ bias, int do_relu)
{
    constexpr int NTILE = 64;
    constexpr int WM = 32;
    constexpr int MT = 2;
    constexpr int A_HI = 0, A_LO = 32768, B_HI = 65536;
    constexpr int B_LO = B_HI + NTILE * 256;

    extern __shared__ char smem[];
    const uint32_t sb = smem_u32(smem);
    const int tid = threadIdx.x, wid = tid >> 5, lane = tid & 31;
    const int m0 = blockIdx.x * 128;
    const int col0 = 0;
    const int wm = wid & 3, wn = wid >> 2;

#pragma unroll
    for (int i = 0; i < 8; i++) {
        int idx = tid + i * 256;
        int r = idx >> 4, kc = idx & 15;
        int gr = m0 + r;
        float4 v0 = make_float4(0.f, 0.f, 0.f, 0.f), v1 = v0;
        if (gr < M) {
            const float* ap = A + (size_t)gr * 128 + kc * 8;
            v0 = *(const float4*)ap;
            v1 = *(const float4*)(ap + 4);
        }
        float f[8] = {v0.x, v0.y, v0.z, v0.w, v1.x, v1.y, v1.z, v1.w};
        uint32_t hw[4], lw[4];
#pragma unroll
        for (int j = 0; j < 4; j++) {
            __nv_bfloat16 h0 = __float2bfloat16(f[2 * j]);
            __nv_bfloat16 h1 = __float2bfloat16(f[2 * j + 1]);
            __nv_bfloat16 l0 = __float2bfloat16(f[2 * j] - __bfloat162float(h0));
            __nv_bfloat16 l1 = __float2bfloat16(f[2 * j + 1] - __bfloat162float(h1));
            hw[j] = pack_bf2(h0, h1);
            lw[j] = pack_bf2(l0, l1);
        }
        uint32_t sw = (uint32_t)(r * 256 + ((kc ^ (r & 7)) << 4));
        *(uint4*)(smem + A_HI + sw) = make_uint4(hw[0], hw[1], hw[2], hw[3]);
        *(uint4*)(smem + A_LO + sw) = make_uint4(lw[0], lw[1], lw[2], lw[3]);
    }
#pragma unroll
    for (int i = 0; i < NTILE / 16; i++) {
        int idx = tid + i * 256;
        int r = idx >> 4, kc = idx & 15;
        uint32_t sw = (uint32_t)(r * 256 + ((kc ^ (r & 7)) << 4));
        *(uint4*)(smem + B_HI + sw) = ((const uint4*)(Bh + (size_t)(col0 + r) * 128))[kc];
        *(uint4*)(smem + B_LO + sw) = ((const uint4*)(Bl + (size_t)(col0 + r) * 128))[kc];
    }
    __syncthreads();

    float acc[MT][4][4];
#pragma unroll
    for (int mt = 0; mt < MT; mt++)
#pragma unroll
        for (int nt = 0; nt < 4; nt++)
#pragma unroll
            for (int j = 0; j < 4; j++) acc[mt][nt][j] = 0.f;

    const int rA = ((lane >> 3) & 1) * 8 + (lane & 7);
    const int cA = lane >> 4;
    const int rB = ((lane >> 4) << 3) + (lane & 7);
    const int cB = (lane >> 3) & 1;

#pragma unroll
    for (int ks = 0; ks < 8; ks++) {
        const int kc0 = ks * 2;
        uint32_t ah[MT][4], al[MT][4], bh[4][2], bl[4][2];
#pragma unroll
        for (int mt = 0; mt < MT; mt++) {
            int row = wm * WM + mt * 16 + rA;
            uint32_t ad = sb + A_HI + row * 256 + (((kc0 + cA) ^ (row & 7)) << 4);
            ldsm_x4(ah[mt][0], ah[mt][1], ah[mt][2], ah[mt][3], ad);
            ldsm_x4(al[mt][0], al[mt][1], al[mt][2], al[mt][3], ad + (A_LO - A_HI));
        }
#pragma unroll
        for (int p = 0; p < 2; p++) {
            int row = wn * 32 + p * 16 + rB;
            uint32_t bd = sb + B_HI + row * 256 + (((kc0 + cB) ^ (row & 7)) << 4);
            uint32_t r0, r1, r2, r3;
            ldsm_x4(r0, r1, r2, r3, bd);
            bh[p * 2][0] = r0; bh[p * 2][1] = r1; bh[p * 2 + 1][0] = r2; bh[p * 2 + 1][1] = r3;
            ldsm_x4(r0, r1, r2, r3, bd + (B_LO - B_HI));
            bl[p * 2][0] = r0; bl[p * 2][1] = r1; bl[p * 2 + 1][0] = r2; bl[p * 2 + 1][1] = r3;
        }
#pragma unroll
        for (int mt = 0; mt < MT; mt++)
#pragma unroll
            for (int nt = 0; nt < 4; nt++) {
                mma16816(acc[mt][nt], ah[mt], bh[nt]);
                mma16816(acc[mt][nt], ah[mt], bl[nt]);
                mma16816(acc[mt][nt], al[mt], bh[nt]);
            }
    }

    const int rowg = lane >> 2, colg = (lane & 3) * 2;
#pragma unroll
    for (int mt = 0; mt < MT; mt++) {
#pragma unroll
        for (int nt = 0; nt < 4; nt++) {
            int gc = col0 + wn * 32 + nt * 8 + colg;
            float bx = 0.f, by = 0.f;
            if (bias) { bx = __ldg(bias + gc); by = __ldg(bias + gc + 1); }
#pragma unroll
            for (int h = 0; h < 2; h++) {
                int gr = m0 + wm * WM + mt * 16 + h * 8 + rowg;
                if (gr < M) {
                    float x = acc[mt][nt][h * 2 + 0] + bx;
                    float y = acc[mt][nt][h * 2 + 1] + by;
                    if (do_relu) { x = fmaxf(x, 0.f); y = fmaxf(y, 0.f); }
                    float2 o; o.x = x; o.y = y;
                    *(float2*)(C + (size_t)gr * ldc + gc) = o;
                }
            }
        }
    }
}

// ---------------- merged weight prep ----------------
__global__ void prep_all(const float* __restrict__ W_m1, const float* __restrict__ W_m2,
                         const float* __restrict__ gik, const float* __restrict__ gir,
                         const float* __restrict__ gck, const float* __restrict__ gcr,
                         const float* __restrict__ Wr1, const float* __restrict__ Wr2)
{
    int idx = blockIdx.x * blockDim.x + threadIdx.x;
    const float* src;
    __nv_bfloat16 *hi, *lo;
    int ldN, l;
    if (idx < 65536) {
        int j = idx >> 14;
        l = idx & 16383;
        ldN = 128;
        if (j == 0)      { src = W_m1;          hi = g_ipcat_h;           lo = g_ipcat_l; }
        else if (j == 1) { src = W_m2 + 16384;  hi = g_ipcat_h + 16384;   lo = g_ipcat_l + 16384; }
        else if (j == 2) { src = W_m1 + 16384;  hi = g_conncat_h;         lo = g_conncat_l; }
        else             { src = W_m2;          hi = g_conncat_h + 16384; lo = g_conncat_l + 16384; }
    } else if (idx < 262144) {
        int t = idx - 65536;
        int j = t / 49152;
        l = t % 49152;
        ldN = 384;
        if (j == 0)      { src = gik; hi = g_gik_h; lo = g_gik_l; }
        else if (j == 1) { src = gir; hi = g_gir_h; lo = g_gir_l; }
        else if (j == 2) { src = gck; hi = g_gck_h; lo = g_gck_l; }
        else             { src = gcr; hi = g_gcr_h; lo = g_gcr_l; }
    } else if (idx < 278528) {
        l = idx - 262144;
        ldN = 128;
        src = Wr1; hi = g_wr1_h; lo = g_wr1_l;
    } else if (idx < 286720) {
        l = idx - 278528;
        ldN = 64;
        src = Wr2; hi = g_wr2_h; lo = g_wr2_l;
    } else {
        return;
    }
    int n = l >> 7, k = l & 127;
    float x = src[(size_t)k * ldN + n];
    __nv_bfloat16 h = __float2bfloat16(x);
    hi[l] = h;
    lo[l] = __float2bfloat16(x - __bfloat162float(h));
}

// ---------------- small utility kernels ----------------
__global__ void init_states(float* __restrict__ ip, float* __restrict__ conn,
                            const float* __restrict__ feat) {
    int i = blockIdx.x * blockDim.x + threadIdx.x;
    if (i < N_CONN * D128) {
        int r = i >> 7, c = i & 127;
        conn[i] = (c < NFEAT) ? feat[r * NFEAT + c] : 0.f;
        if (i < N_IP * D128) ip[i] = 1.f;
    }
}
__global__ void zero_rc(float* __restrict__ c1, float* __restrict__ c2) {
    int i = blockIdx.x * blockDim.x + threadIdx.x;
    if (i < N_CONN) c1[i] = 0.f;
    if (i < N_IP) c2[i] = 0.f;
}
__global__ void count2(const int* __restrict__ d1, const int* __restrict__ d2,
                       float* __restrict__ c1, float* __restrict__ c2) {
    int i = blockIdx.x * blockDim.x + threadIdx.x;
    if (i < N_E) atomicAdd(c1 + d1[i], 1.f);
    else if (i < 2 * N_E) atomicAdd(c2 + d2[i - N_E], 1.f);
}
__global__ void recip2(float* __restrict__ c1, float* __restrict__ c2) {
    int i = blockIdx.x * blockDim.x + threadIdx.x;
    if (i < N_CONN) c1[i] = 1.f / fmaxf(c1[i], 1.f);
    if (i < N_IP) c2[i] = 1.f / fmaxf(c2[i], 1.f);
}
__global__ void zero2(float* __restrict__ a, int n4a, float* __restrict__ b, int n4b) {
    int i = blockIdx.x * blockDim.x + threadIdx.x;
    if (i < n4a) *(float4*)(a + (size_t)i * 4) = make_float4(0.f, 0.f, 0.f, 0.f);
    else if (i < n4a + n4b)
        *(float4*)(b + (size_t)(i - n4a) * 4) = make_float4(0.f, 0.f, 0.f, 0.f);
}

// ---------------- merged edge message + scatter-add (both directions, one launch) --------
__global__ void edge_msg2x(
    const int* __restrict__ s0, const int* __restrict__ d0,
    const int* __restrict__ s1, const int* __restrict__ d1,
    const float* __restrict__ XS0, const float* __restrict__ XD0,
    const float* __restrict__ XS1, const float* __restrict__ XD1,
    const float* __restrict__ b0, const float* __restrict__ b1,
    float* __restrict__ out0, float* __restrict__ out1)
{
    int gw = (blockIdx.x * blockDim.x + threadIdx.x) >> 5;
    int lane = threadIdx.x & 31;
    const int* srcp;
    const int* dstp;
    const float *XS, *XD, *bias;
    float* outp;
    if (gw < N_E) {
        srcp = s0; dstp = d0; XS = XS0; XD = XD0; bias = b0; outp = out0;
    } else {
        gw -= N_E;
        if (gw >= N_E) return;
        srcp = s1; dstp = d1; XS = XS1; XD = XD1; bias = b1; outp = out1;
    }
    int s = __ldg(srcp + gw);
    int d = __ldg(dstp + gw);
    int c = lane << 2;
    float4 a = *(const float4*)(XS + (size_t)s * 256 + c);
    float4 b = *(const float4*)(XD + (size_t)d * 256 + c);
    float4 bb = *(const float4*)(bias + c);
    float4 m;
    m.x = fmaxf(a.x + b.x + bb.x, 0.f);
    m.y = fmaxf(a.y + b.y + bb.y, 0.f);
    m.z = fmaxf(a.z + b.z + bb.z, 0.f);
    m.w = fmaxf(a.w + b.w + bb.w, 0.f);
    float* p = outp + (size_t)d * 128 + c;
    atomicAdd(p + 0, m.x);
    atomicAdd(p + 1, m.y);
    atomicAdd(p + 2, m.z);
    atomicAdd(p + 3, m.w);
}

// ---------------- merged GRU gate (ip + conn, one launch) ----------------
__device__ __forceinline__ float gru1(float xz, float hz, float xr, float hr,
                                      float xh, float hh, float h) {
    float z = 1.f / (1.f + expf(-(xz + hz)));
    float r = 1.f / (1.f + expf(-(xr + hr)));
    float c = tanhf(xh + r * hh);
    return z * h + (1.f - z) * c;
}
__global__ void gru_gate2x(float* __restrict__ h0, const float* __restrict__ xm0,
                           const float* __restrict__ hm0,
                           float* __restrict__ h1, const float* __restrict__ xm1,
                           const float* __restrict__ hm1)
{
    int idx = blockIdx.x * blockDim.x + threadIdx.x;
    float* h;
    const float *xm, *hm;
    if (idx < N_IP * 32) {
        h = h0; xm = xm0; hm = hm0;
    } else {
        idx -= N_IP * 32;
        if (idx >= N_CONN * 32) return;
        h = h1; xm = xm1; hm = hm1;
    }
    int row = idx >> 5;
    int c = (idx & 31) << 2;
    const float* x = xm + (size_t)row * 384;
    const float* hh = hm + (size_t)row * 384;
    float4 xz = *(const float4*)(x + c);
    float4 xr = *(const float4*)(x + 128 + c);
    float4 xh = *(const float4*)(x + 256 + c);
    float4 hz = *(const float4*)(hh + c);
    float4 hr = *(const float4*)(hh + 128 + c);
    float4 hc = *(const float4*)(hh + 256 + c);
    float* hp = h + (size_t)row * 128 + c;
    float4 hv = *(const float4*)hp;
    float4 o;
    o.x = gru1(xz.x, hz.x, xr.x, hr.x, xh.x, hc.x, hv.x);
    o.y = gru1(xz.y, hz.y, xr.y, hr.y, xh.y, hc.y, hv.y);
    o.z = gru1(xz.z, hz.z, xr.z, hr.z, xh.z, hc.z, hv.z);
    o.w = gru1(xz.w, hz.w, xr.w, hr.w, xh.w, hc.w, hv.w);
    *(float4*)hp = o;
}

// ---------------- readout tail ----------------
__global__ void readout_kernel(const float* __restrict__ H2, const float* __restrict__ W3,
                               const float* __restrict__ b3, float* __restrict__ out, int M)
{
    __shared__ float w[64 * 15];
    __shared__ float bb[15];
    for (int i = threadIdx.x; i < 64 * 15; i += blockDim.x) w[i] = W3[i];
    if (threadIdx.x < 15) bb[threadIdx.x] = b3[threadIdx.x];
    __syncthreads();
    int row = blockIdx.x * blockDim.x + threadIdx.x;
    if (row >= M) return;
    float acc[15];
#pragma unroll
    for (int j = 0; j < 15; j++) acc[j] = bb[j];
    const float* hrow = H2 + (size_t)row * 64;
#pragma unroll 16
    for (int k = 0; k < 64; k++) {
        float hv = __ldg(hrow + k);
#pragma unroll
        for (int j = 0; j < 15; j++) acc[j] += hv * w[k * 15 + j];
    }
    float mx = acc[0];
#pragma unroll
    for (int j = 1; j < 15; j++) mx = fmaxf(mx, acc[j]);
    float sum = 0.f;
#pragma unroll
    for (int j = 0; j < 15; j++) { acc[j] = expf(acc[j] - mx); sum += acc[j]; }
    float inv = 1.f / sum;
    float* op = out + (size_t)row * 15;
#pragma unroll
    for (int j = 0; j < 15; j++) op[j] = acc[j] * inv;
}

// ---------------- host side ----------------
static const int SMEM128 = 65536 + 128 * 512;  // 131072
static const int SMEM64  = 65536 + 64 * 512;   // 98304
static const int MB_CONN = (N_CONN + 127) / 128;  // 782

extern "C" void kernel_launch(void* const* d_in, const int* in_sizes, int n_in,
                              void* d_out, int out_size)
{
    const float* feat  = (const float*)d_in[0];
    const int*   s_i2c = (const int*)d_in[1];
    const int*   d_i2c = (const int*)d_in[2];
    const int*   s_c2i = (const int*)d_in[3];
    const int*   d_c2i = (const int*)d_in[4];
    const float* W_m1  = (const float*)d_in[5];
    const float* b_m1  = (const float*)d_in[6];
    const float* W_m2  = (const float*)d_in[7];
    const float* b_m2  = (const float*)d_in[8];
    const float* gik   = (const float*)d_in[9];
    const float* gir   = (const float*)d_in[10];
    const float* gib   = (const float*)d_in[11];
    const float* gck   = (const float*)d_in[12];
    const float* gcr   = (const float*)d_in[13];
    const float* gcb   = (const float*)d_in[14];
    const float* Wr1   = (const float*)d_in[15];
    const float* br1   = (const float*)d_in[16];
    const float* Wr2   = (const float*)d_in[17];
    const float* br2   = (const float*)d_in[18];
    const float* Wr3   = (const float*)d_in[19];
    const float* br3   = (const float*)d_in[20];
    float* out = (float*)d_out;

    cudaFuncSetAttribute(mma_gemm_z, cudaFuncAttributeMaxDynamicSharedMemorySize, SMEM128);
    cudaFuncSetAttribute(mma_gemm64, cudaFuncAttributeMaxDynamicSharedMemorySize, SMEM64);

    void* p;
    cudaGetSymbolAddress(&p, g_ip);       float* ip       = (float*)p;
    cudaGetSymbolAddress(&p, g_conn);     float* conn     = (float*)p;
    cudaGetSymbolAddress(&p, g_msg_ip);   float* msg_ip   = (float*)p;
    cudaGetSymbolAddress(&p, g_msg_conn); float* msg_conn = (float*)p;
    cudaGetSymbolAddress(&p, g_agg_conn); float* agg_conn = (float*)p;
    cudaGetSymbolAddress(&p, g_agg_ip);   float* agg_ip   = (float*)p;
    cudaGetSymbolAddress(&p, g_xm_ip);    float* xm_ip    = (float*)p;
    cudaGetSymbolAddress(&p, g_hm_ip);    float* hm_ip    = (float*)p;
    cudaGetSymbolAddress(&p, g_xm_c);     float* xm_c     = (float*)p;
    cudaGetSymbolAddress(&p, g_hm_c);     float* hm_c     = (float*)p;
    cudaGetSymbolAddress(&p, g_rc_conn);  float* rc_conn  = (float*)p;
    cudaGetSymbolAddress(&p, g_rc_ip);    float* rc_ip    = (float*)p;
    cudaGetSymbolAddress(&p, g_H1);       float* H1       = (float*)p;
    cudaGetSymbolAddress(&p, g_H2);       float* H2       = (float*)p;

    __nv_bfloat16 *ipcat_h, *ipcat_l, *conncat_h, *conncat_l;
    __nv_bfloat16 *gik_h, *gik_l, *gir_h, *gir_l, *gck_h, *gck_l, *gcr_h, *gcr_l;
    __nv_bfloat16 *wr1_h, *wr1_l, *wr2_h, *wr2_l;
    cudaGetSymbolAddress(&p, g_ipcat_h);   ipcat_h   = (__nv_bfloat16*)p;
    cudaGetSymbolAddress(&p, g_ipcat_l);   ipcat_l   = (__nv_bfloat16*)p;
    cudaGetSymbolAddress(&p, g_conncat_h); conncat_h = (__nv_bfloat16*)p;
    cudaGetSymbolAddress(&p, g_conncat_l); conncat_l = (__nv_bfloat16*)p;
    cudaGetSymbolAddress(&p, g_gik_h); gik_h = (__nv_bfloat16*)p;
    cudaGetSymbolAddress(&p, g_gik_l); gik_l = (__nv_bfloat16*)p;
    cudaGetSymbolAddress(&p, g_gir_h); gir_h = (__nv_bfloat16*)p;
    cudaGetSymbolAddress(&p, g_gir_l); gir_l = (__nv_bfloat16*)p;
    cudaGetSymbolAddress(&p, g_gck_h); gck_h = (__nv_bfloat16*)p;
    cudaGetSymbolAddress(&p, g_gck_l); gck_l = (__nv_bfloat16*)p;
    cudaGetSymbolAddress(&p, g_gcr_h); gcr_h = (__nv_bfloat16*)p;
    cudaGetSymbolAddress(&p, g_gcr_l); gcr_l = (__nv_bfloat16*)p;
    cudaGetSymbolAddress(&p, g_wr1_h); wr1_h = (__nv_bfloat16*)p;
    cudaGetSymbolAddress(&p, g_wr1_l); wr1_l = (__nv_bfloat16*)p;
    cudaGetSymbolAddress(&p, g_wr2_h); wr2_h = (__nv_bfloat16*)p;
    cudaGetSymbolAddress(&p, g_wr2_l); wr2_l = (__nv_bfloat16*)p;

    // --- merged weight prep ---
    prep_all<<<(286720 + 255) / 256, 256>>>(W_m1, W_m2, gik, gir, gck, gcr, Wr1, Wr2);

    // --- segment counts + state init ---
    zero_rc<<<(N_CONN + 255) / 256, 256>>>(rc_conn, rc_ip);
    count2<<<(2 * N_E + 255) / 256, 256>>>(d_i2c, d_c2i, rc_conn, rc_ip);
    recip2<<<(N_CONN + 255) / 256, 256>>>(rc_conn, rc_ip);
    init_states<<<(N_CONN * D128 + 255) / 256, 256>>>(ip, conn, feat);

    const int edge_blocks = (2 * N_E * 32 + 255) / 256;
    const int z4c = N_CONN * 32, z4i = N_IP * 32;
    const int gate_threads = (N_IP + N_CONN) * 32;

    for (int t = 0; t < T_ITERS; t++) {
        // merged message GEMMs: z0 = ip @ ipcat (M=N_IP), z1 = conn @ conncat (M=N_CONN)
        {
            dim3 g(MB_CONN, 2, 2);
            mma_gemm_z<<<g, 256, SMEM128>>>(
                ip, conn, nullptr, nullptr,
                ipcat_h, conncat_h, nullptr, nullptr,
                ipcat_l, conncat_l, nullptr, nullptr,
                msg_ip, msg_conn, nullptr, nullptr,
                N_IP, N_CONN, 0, 0,
                nullptr, nullptr, nullptr, nullptr,
                nullptr, nullptr, nullptr, nullptr,
                256, 0);
        }

        zero2<<<(z4c + z4i + 255) / 256, 256>>>(agg_conn, z4c, agg_ip, z4i);

        // merged edge kernels (both directions)
        edge_msg2x<<<edge_blocks, 256>>>(s_i2c, d_i2c, s_c2i, d_c2i,
                                         msg_ip, msg_conn, msg_conn + 128, msg_ip + 128,
                                         b_m1, b_m2, agg_conn, agg_ip);

        // merged GRU GEMMs: z0=xm_ip, z1=hm_ip, z2=xm_c, z3=hm_c
        {
            dim3 g(MB_CONN, 3, 4);
            mma_gemm_z<<<g, 256, SMEM128>>>(
                agg_ip, ip, agg_conn, conn,
                gik_h, gir_h, gck_h, gcr_h,
                gik_l, gir_l, gck_l, gcr_l,
                xm_ip, hm_ip, xm_c, hm_c,
                N_IP, N_IP, N_CONN, N_CONN,
                gib, gib + 384, gcb, gcb + 384,
                rc_ip, nullptr, rc_conn, nullptr,
                384, 0);
        }

        // merged gate update (in place)
        gru_gate2x<<<(gate_threads + 255) / 256, 256>>>(ip, xm_ip, hm_ip, conn, xm_c, hm_c);
    }

    // --- readout ---
    {
        dim3 g(MB_CONN, 1, 1);
        mma_gemm_z<<<g, 256, SMEM128>>>(
            conn, nullptr, nullptr, nullptr,
            wr1_h, nullptr, nullptr, nullptr,
            wr1_l, nullptr, nullptr, nullptr,
            H1, nullptr, nullptr, nullptr,
            N_CONN, 0, 0, 0,
            br1, nullptr, nullptr, nullptr,
            nullptr, nullptr, nullptr, nullptr,
            128, 1);
    }
    mma_gemm64<<<MB_CONN, 256, SMEM64>>>(H1, wr2_h, wr2_l, H2, N_CONN, 64, br2, 1);
    readout_kernel<<<(N_CONN + 127) / 128, 128>>>(H2, Wr3, br3, out, N_CONN);
}

// round 13
// speedup vs baseline: 1.2046x; 1.2046x over previous
#include <cuda_runtime.h>
#include <cuda_bf16.h>
#include <cstdint>
#include <cstddef>

#define D128 128
#define NFEAT 10
#define N_IP 20000
#define N_CONN 100000
#define N_E 200000
#define T_ITERS 3

// ---------------- scratch (static device globals; no allocation) ----------------
__device__ float g_ip[N_IP * D128];
__device__ float g_conn[N_CONN * D128];
__device__ float g_msg_ip[N_IP * 256];      // [XA | YB]
__device__ float g_msg_conn[N_CONN * 256];  // [XB | YA]
__device__ float g_agg_conn[N_CONN * D128];
__device__ float g_agg_ip[N_IP * D128];
__device__ float g_xm_ip[N_IP * 384];
__device__ float g_hm_ip[N_IP * 384];
__device__ float g_xm_c[N_CONN * 384];
__device__ float g_hm_c[N_CONN * 384];
__device__ float g_rc_conn[N_CONN];
__device__ float g_rc_ip[N_IP];
__device__ float g_H1[N_CONN * D128];
__device__ float g_H2[N_CONN * 64];

// bf16 hi/lo split, transposed weights [N][128]
__device__ __nv_bfloat16 g_ipcat_h[256 * 128], g_ipcat_l[256 * 128];    // [XA w | YB w]
__device__ __nv_bfloat16 g_conncat_h[256 * 128], g_conncat_l[256 * 128];// [XB w | YA w]
__device__ __nv_bfloat16 g_gik_h[384 * 128], g_gik_l[384 * 128];
__device__ __nv_bfloat16 g_gir_h[384 * 128], g_gir_l[384 * 128];
__device__ __nv_bfloat16 g_gck_h[384 * 128], g_gck_l[384 * 128];
__device__ __nv_bfloat16 g_gcr_h[384 * 128], g_gcr_l[384 * 128];
__device__ __nv_bfloat16 g_wr1_h[128 * 128], g_wr1_l[128 * 128];
__device__ __nv_bfloat16 g_wr2_h[64 * 128],  g_wr2_l[64 * 128];

// ---------------- helpers ----------------
__device__ __forceinline__ uint32_t smem_u32(const void* p) {
    uint32_t a;
    asm("{ .reg .u64 t; cvta.to.shared.u64 t, %1; cvt.u32.u64 %0, t; }" : "=r"(a) : "l"(p));
    return a;
}
__device__ __forceinline__ void ldsm_x4(uint32_t& r0, uint32_t& r1, uint32_t& r2, uint32_t& r3,
                                        uint32_t addr) {
    asm volatile("ldmatrix.sync.aligned.m8n8.x4.shared.b16 {%0,%1,%2,%3}, [%4];"
                 : "=r"(r0), "=r"(r1), "=r"(r2), "=r"(r3) : "r"(addr));
}
__device__ __forceinline__ void mma16816(float* c, const uint32_t* a, const uint32_t* b) {
    asm volatile(
        "mma.sync.aligned.m16n8k16.row.col.f32.bf16.bf16.f32 "
        "{%0,%1,%2,%3}, {%4,%5,%6,%7}, {%8,%9}, {%0,%1,%2,%3};"
        : "+f"(c[0]), "+f"(c[1]), "+f"(c[2]), "+f"(c[3])
        : "r"(a[0]), "r"(a[1]), "r"(a[2]), "r"(a[3]), "r"(b[0]), "r"(b[1]));
}
__device__ __forceinline__ uint32_t pack_bf2(__nv_bfloat16 a, __nv_bfloat16 b) {
    return ((uint32_t)__bfloat16_as_ushort(b) << 16) | (uint32_t)__bfloat16_as_ushort(a);
}

// ---------------- HMMA GEMM (R5/R11-proven, single pass, untouched) ----------------
// C[MxNtot] = act(rowscale(A[Mx128]) @ Wt^T + bias); Wt = [Ntot x 128] bf16 hi/lo.
template <int NTILE>
__global__ __launch_bounds__(256) void mma_gemm(
    const float* __restrict__ A, const __nv_bfloat16* __restrict__ Bh,
    const __nv_bfloat16* __restrict__ Bl, float* __restrict__ C,
    int M, int ldc, const float* __restrict__ bias,
    const float* __restrict__ rscale, int do_relu)
{
    constexpr int WM = (NTILE == 128) ? 64 : 32;
    constexpr int MT = WM / 16;
    constexpr int A_HI = 0, A_LO = 32768, B_HI = 65536;
    constexpr int B_LO = B_HI + NTILE * 256;

    extern __shared__ char smem[];
    const uint32_t sb = smem_u32(smem);
    const int tid = threadIdx.x, wid = tid >> 5, lane = tid & 31;
    const int m0 = blockIdx.x * 128;
    const int col0 = blockIdx.y * NTILE;
    int wm, wn;
    if (NTILE == 128) { wm = wid & 1; wn = wid >> 1; }
    else              { wm = wid & 3; wn = wid >> 2; }

#pragma unroll
    for (int i = 0; i < 8; i++) {
        int idx = tid + i * 256;
        int r = idx >> 4, kc = idx & 15;
        int gr = m0 + r;
        float4 v0 = make_float4(0.f, 0.f, 0.f, 0.f), v1 = v0;
        if (gr < M) {
            const float* ap = A + (size_t)gr * 128 + kc * 8;
            v0 = *(const float4*)ap;
            v1 = *(const float4*)(ap + 4);
            if (rscale) {
                float s = rscale[gr];
                v0.x *= s; v0.y *= s; v0.z *= s; v0.w *= s;
                v1.x *= s; v1.y *= s; v1.z *= s; v1.w *= s;
            }
        }
        float f[8] = {v0.x, v0.y, v0.z, v0.w, v1.x, v1.y, v1.z, v1.w};
        uint32_t hw[4], lw[4];
#pragma unroll
        for (int j = 0; j < 4; j++) {
            __nv_bfloat16 h0 = __float2bfloat16(f[2 * j]);
            __nv_bfloat16 h1 = __float2bfloat16(f[2 * j + 1]);
            __nv_bfloat16 l0 = __float2bfloat16(f[2 * j] - __bfloat162float(h0));
            __nv_bfloat16 l1 = __float2bfloat16(f[2 * j + 1] - __bfloat162float(h1));
            hw[j] = pack_bf2(h0, h1);
            lw[j] = pack_bf2(l0, l1);
        }
        uint32_t sw = (uint32_t)(r * 256 + ((kc ^ (r & 7)) << 4));
        *(uint4*)(smem + A_HI + sw) = make_uint4(hw[0], hw[1], hw[2], hw[3]);
        *(uint4*)(smem + A_LO + sw) = make_uint4(lw[0], lw[1], lw[2], lw[3]);
    }
#pragma unroll
    for (int i = 0; i < NTILE / 16; i++) {
        int idx = tid + i * 256;
        int r = idx >> 4, kc = idx & 15;
        uint32_t sw = (uint32_t)(r * 256 + ((kc ^ (r & 7)) << 4));
        *(uint4*)(smem + B_HI + sw) = ((const uint4*)(Bh + (size_t)(col0 + r) * 128))[kc];
        *(uint4*)(smem + B_LO + sw) = ((const uint4*)(Bl + (size_t)(col0 + r) * 128))[kc];
    }
    __syncthreads();

    float acc[MT][4][4];
#pragma unroll
    for (int mt = 0; mt < MT; mt++)
#pragma unroll
        for (int nt = 0; nt < 4; nt++)
#pragma unroll
            for (int j = 0; j < 4; j++) acc[mt][nt][j] = 0.f;

    const int rA = ((lane >> 3) & 1) * 8 + (lane & 7);
    const int cA = lane >> 4;
    const int rB = ((lane >> 4) << 3) + (lane & 7);
    const int cB = (lane >> 3) & 1;

#pragma unroll
    for (int ks = 0; ks < 8; ks++) {
        const int kc0 = ks * 2;
        uint32_t ah[MT][4], al[MT][4], bh[4][2], bl[4][2];
#pragma unroll
        for (int mt = 0; mt < MT; mt++) {
            int row = wm * WM + mt * 16 + rA;
            uint32_t ad = sb + A_HI + row * 256 + (((kc0 + cA) ^ (row & 7)) << 4);
            ldsm_x4(ah[mt][0], ah[mt][1], ah[mt][2], ah[mt][3], ad);
            ldsm_x4(al[mt][0], al[mt][1], al[mt][2], al[mt][3], ad + (A_LO - A_HI));
        }
#pragma unroll
        for (int p = 0; p < 2; p++) {
            int row = wn * 32 + p * 16 + rB;
            uint32_t bd = sb + B_HI + row * 256 + (((kc0 + cB) ^ (row & 7)) << 4);
            uint32_t r0, r1, r2, r3;
            ldsm_x4(r0, r1, r2, r3, bd);
            bh[p * 2][0] = r0; bh[p * 2][1] = r1; bh[p * 2 + 1][0] = r2; bh[p * 2 + 1][1] = r3;
            ldsm_x4(r0, r1, r2, r3, bd + (B_LO - B_HI));
            bl[p * 2][0] = r0; bl[p * 2][1] = r1; bl[p * 2 + 1][0] = r2; bl[p * 2 + 1][1] = r3;
        }
#pragma unroll
        for (int mt = 0; mt < MT; mt++)
#pragma unroll
            for (int nt = 0; nt < 4; nt++) {
                mma16816(acc[mt][nt], ah[mt], bh[nt]);
                mma16816(acc[mt][nt], ah[mt], bl[nt]);
                mma16816(acc[mt][nt], al[mt], bh[nt]);
            }
    }

    const int rowg = lane >> 2, colg = (lane & 3) * 2;
#pragma unroll
    for (int mt = 0; mt < MT; mt++) {
#pragma unroll
        for (int nt = 0; nt < 4; nt++) {
            int gc = col0 + wn * 32 + nt * 8 + colg;
            float bx = 0.f, by = 0.f;
            if (bias) { bx = __ldg(bias + gc); by = __ldg(bias + gc + 1); }
#pragma unroll
            for (int h = 0; h < 2; h++) {
                int gr = m0 + wm * WM + mt * 16 + h * 8 + rowg;
                if (gr < M) {
                    float x = acc[mt][nt][h * 2 + 0] + bx;
                    float y = acc[mt][nt][h * 2 + 1] + by;
                    if (do_relu) { x = fmaxf(x, 0.f); y = fmaxf(y, 0.f); }
                    float2 o; o.x = x; o.y = y;
                    *(float2*)(C + (size_t)gr * ldc + gc) = o;
                }
            }
        }
    }
}

// ---------------- merged weight prep: transposes + bf16 hi/lo split, one launch ----------
__global__ void prep_all(const float* __restrict__ W_m1, const float* __restrict__ W_m2,
                         const float* __restrict__ gik, const float* __restrict__ gir,
                         const float* __restrict__ gck, const float* __restrict__ gcr,
                         const float* __restrict__ Wr1, const float* __restrict__ Wr2)
{
    int idx = blockIdx.x * blockDim.x + threadIdx.x;
    const float* src;
    __nv_bfloat16 *hi, *lo;
    int ldN, l;
    if (idx < 65536) {                       // 4 jobs x 16384 (128x128 each)
        int j = idx >> 14;
        l = idx & 16383;
        ldN = 128;
        if (j == 0)      { src = W_m1;          hi = g_ipcat_h;           lo = g_ipcat_l; }
        else if (j == 1) { src = W_m2 + 16384;  hi = g_ipcat_h + 16384;   lo = g_ipcat_l + 16384; }
        else if (j == 2) { src = W_m1 + 16384;  hi = g_conncat_h;         lo = g_conncat_l; }
        else             { src = W_m2;          hi = g_conncat_h + 16384; lo = g_conncat_l + 16384; }
    } else if (idx < 262144) {               // 4 jobs x 49152 (384x128 each)
        int t = idx - 65536;
        int j = t / 49152;
        l = t % 49152;
        ldN = 384;
        if (j == 0)      { src = gik; hi = g_gik_h; lo = g_gik_l; }
        else if (j == 1) { src = gir; hi = g_gir_h; lo = g_gir_l; }
        else if (j == 2) { src = gck; hi = g_gck_h; lo = g_gck_l; }
        else             { src = gcr; hi = g_gcr_h; lo = g_gcr_l; }
    } else if (idx < 278528) {               // Wr1: 16384
        l = idx - 262144;
        ldN = 128;
        src = Wr1; hi = g_wr1_h; lo = g_wr1_l;
    } else if (idx < 286720) {               // Wr2: 8192
        l = idx - 278528;
        ldN = 64;
        src = Wr2; hi = g_wr2_h; lo = g_wr2_l;
    } else {
        return;
    }
    int n = l >> 7, k = l & 127;
    float x = src[(size_t)k * ldN + n];
    __nv_bfloat16 h = __float2bfloat16(x);
    hi[l] = h;
    lo[l] = __float2bfloat16(x - __bfloat162float(h));
}

// ---------------- small utility kernels ----------------
__global__ void init_states(float* __restrict__ ip, float* __restrict__ conn,
                            const float* __restrict__ feat) {
    int i = blockIdx.x * blockDim.x + threadIdx.x;
    if (i < N_CONN * D128) {
        int r = i >> 7, c = i & 127;
        conn[i] = (c < NFEAT) ? feat[r * NFEAT + c] : 0.f;
        if (i < N_IP * D128) ip[i] = 1.f;
    }
}
__global__ void zero_rc(float* __restrict__ c1, float* __restrict__ c2) {
    int i = blockIdx.x * blockDim.x + threadIdx.x;
    if (i < N_CONN) c1[i] = 0.f;
    if (i < N_IP) c2[i] = 0.f;
}
__global__ void count2(const int* __restrict__ d1, const int* __restrict__ d2,
                       float* __restrict__ c1, float* __restrict__ c2) {
    int i = blockIdx.x * blockDim.x + threadIdx.x;
    if (i < N_E) atomicAdd(c1 + d1[i], 1.f);
    else if (i < 2 * N_E) atomicAdd(c2 + d2[i - N_E], 1.f);
}
__global__ void recip2(float* __restrict__ c1, float* __restrict__ c2) {
    int i = blockIdx.x * blockDim.x + threadIdx.x;
    if (i < N_CONN) c1[i] = 1.f / fmaxf(c1[i], 1.f);
    if (i < N_IP) c2[i] = 1.f / fmaxf(c2[i], 1.f);
}
__global__ void zero2(float* __restrict__ a, int n4a, float* __restrict__ b, int n4b) {
    int i = blockIdx.x * blockDim.x + threadIdx.x;
    if (i < n4a) *(float4*)(a + (size_t)i * 4) = make_float4(0.f, 0.f, 0.f, 0.f);
    else if (i < n4a + n4b)
        *(float4*)(b + (size_t)(i - n4a) * 4) = make_float4(0.f, 0.f, 0.f, 0.f);
}

// ---------------- edge message + scatter-add (vectorized red.v4) ----------------
__global__ void edge_msg_kernel(
    const int* __restrict__ src, const int* __restrict__ dst,
    const float* __restrict__ XS, const float* __restrict__ XD, int ld,
    const float* __restrict__ bias, float* __restrict__ out_sum, int e)
{
    int gw = (blockIdx.x * blockDim.x + threadIdx.x) >> 5;
    if (gw >= e) return;
    int lane = threadIdx.x & 31;
    int s = __ldg(src + gw);
    int d = __ldg(dst + gw);
    int c = lane << 2;
    float4 a = *(const float4*)(XS + (size_t)s * ld + c);
    float4 b = *(const float4*)(XD + (size_t)d * ld + c);
    float4 bb = *(const float4*)(bias + c);
    float4 m;
    m.x = fmaxf(a.x + b.x + bb.x, 0.f);
    m.y = fmaxf(a.y + b.y + bb.y, 0.f);
    m.z = fmaxf(a.z + b.z + bb.z, 0.f);
    m.w = fmaxf(a.w + b.w + bb.w, 0.f);
    float* p = out_sum + (size_t)d * 128 + c;
    asm volatile("red.global.add.v4.f32 [%0], {%1, %2, %3, %4};"
                 :: "l"(p), "f"(m.x), "f"(m.y), "f"(m.z), "f"(m.w) : "memory");
}

// ---------------- GRU gate fusion (R5/R11) ----------------
__device__ __forceinline__ float gru1(float xz, float hz, float xr, float hr,
                                      float xh, float hh, float h) {
    float z = 1.f / (1.f + expf(-(xz + hz)));
    float r = 1.f / (1.f + expf(-(xr + hr)));
    float c = tanhf(xh + r * hh);
    return z * h + (1.f - z) * c;
}
__global__ void gru_gate_kernel(float* __restrict__ h, const float* __restrict__ xm,
                                const float* __restrict__ hm, int M)
{
    int idx = blockIdx.x * blockDim.x + threadIdx.x;
    if (idx >= M * 32) return;
    int row = idx >> 5;
    int c = (idx & 31) << 2;
    const float* x = xm + (size_t)row * 384;
    const float* hh = hm + (size_t)row * 384;
    float4 xz = *(const float4*)(x + c);
    float4 xr = *(const float4*)(x + 128 + c);
    float4 xh = *(const float4*)(x + 256 + c);
    float4 hz = *(const float4*)(hh + c);
    float4 hr = *(const float4*)(hh + 128 + c);
    float4 hc = *(const float4*)(hh + 256 + c);
    float* hp = h + (size_t)row * 128 + c;
    float4 hv = *(const float4*)hp;
    float4 o;
    o.x = gru1(xz.x, hz.x, xr.x, hr.x, xh.x, hc.x, hv.x);
    o.y = gru1(xz.y, hz.y, xr.y, hr.y, xh.y, hc.y, hv.y);
    o.z = gru1(xz.z, hz.z, xr.z, hr.z, xh.z, hc.z, hv.z);
    o.w = gru1(xz.w, hz.w, xr.w, hr.w, xh.w, hc.w, hv.w);
    *(float4*)hp = o;
}

// ---------------- readout tail ----------------
__global__ void readout_kernel(const float* __restrict__ H2, const float* __restrict__ W3,
                               const float* __restrict__ b3, float* __restrict__ out, int M)
{
    __shared__ float w[64 * 15];
    __shared__ float bb[15];
    for (int i = threadIdx.x; i < 64 * 15; i += blockDim.x) w[i] = W3[i];
    if (threadIdx.x < 15) bb[threadIdx.x] = b3[threadIdx.x];
    __syncthreads();
    int row = blockIdx.x * blockDim.x + threadIdx.x;
    if (row >= M) return;
    float acc[15];
#pragma unroll
    for (int j = 0; j < 15; j++) acc[j] = bb[j];
    const float* hrow = H2 + (size_t)row * 64;
#pragma unroll 16
    for (int k = 0; k < 64; k++) {
        float hv = __ldg(hrow + k);
#pragma unroll
        for (int j = 0; j < 15; j++) acc[j] += hv * w[k * 15 + j];
    }
    float mx = acc[0];
#pragma unroll
    for (int j = 1; j < 15; j++) mx = fmaxf(mx, acc[j]);
    float sum = 0.f;
#pragma unroll
    for (int j = 0; j < 15; j++) { acc[j] = expf(acc[j] - mx); sum += acc[j]; }
    float inv = 1.f / sum;
    float* op = out + (size_t)row * 15;
#pragma unroll
    for (int j = 0; j < 15; j++) op[j] = acc[j] * inv;
}

// ---------------- host side ----------------
static const int SMEM128 = 65536 + 128 * 512;  // 131072
static const int SMEM64  = 65536 + 64 * 512;   // 98304

static inline void launch_g128(const float* A, const __nv_bfloat16* Bh, const __nv_bfloat16* Bl,
                               float* C, int M, int Ntot, int ldc, const float* bias,
                               const float* rs, int relu) {
    dim3 g((M + 127) / 128, Ntot / 128);
    mma_gemm<128><<<g, 256, SMEM128>>>(A, Bh, Bl, C, M, ldc, bias, rs, relu);
}

extern "C" void kernel_launch(void* const* d_in, const int* in_sizes, int n_in,
                              void* d_out, int out_size)
{
    const float* feat  = (const float*)d_in[0];
    const int*   s_i2c = (const int*)d_in[1];
    const int*   d_i2c = (const int*)d_in[2];
    const int*   s_c2i = (const int*)d_in[3];
    const int*   d_c2i = (const int*)d_in[4];
    const float* W_m1  = (const float*)d_in[5];
    const float* b_m1  = (const float*)d_in[6];
    const float* W_m2  = (const float*)d_in[7];
    const float* b_m2  = (const float*)d_in[8];
    const float* gik   = (const float*)d_in[9];
    const float* gir   = (const float*)d_in[10];
    const float* gib   = (const float*)d_in[11];
    const float* gck   = (const float*)d_in[12];
    const float* gcr   = (const float*)d_in[13];
    const float* gcb   = (const float*)d_in[14];
    const float* Wr1   = (const float*)d_in[15];
    const float* br1   = (const float*)d_in[16];
    const float* Wr2   = (const float*)d_in[17];
    const float* br2   = (const float*)d_in[18];
    const float* Wr3   = (const float*)d_in[19];
    const float* br3   = (const float*)d_in[20];
    float* out = (float*)d_out;

    cudaFuncSetAttribute(mma_gemm<128>, cudaFuncAttributeMaxDynamicSharedMemorySize, SMEM128);
    cudaFuncSetAttribute(mma_gemm<64>,  cudaFuncAttributeMaxDynamicSharedMemorySize, SMEM64);

    void* p;
    cudaGetSymbolAddress(&p, g_ip);       float* ip       = (float*)p;
    cudaGetSymbolAddress(&p, g_conn);     float* conn     = (float*)p;
    cudaGetSymbolAddress(&p, g_msg_ip);   float* msg_ip   = (float*)p;
    cudaGetSymbolAddress(&p, g_msg_conn); float* msg_conn = (float*)p;
    cudaGetSymbolAddress(&p, g_agg_conn); float* agg_conn = (float*)p;
    cudaGetSymbolAddress(&p, g_agg_ip);   float* agg_ip   = (float*)p;
    cudaGetSymbolAddress(&p, g_xm_ip);    float* xm_ip    = (float*)p;
    cudaGetSymbolAddress(&p, g_hm_ip);    float* hm_ip    = (float*)p;
    cudaGetSymbolAddress(&p, g_xm_c);     float* xm_c     = (float*)p;
    cudaGetSymbolAddress(&p, g_hm_c);     float* hm_c     = (float*)p;
    cudaGetSymbolAddress(&p, g_rc_conn);  float* rc_conn  = (float*)p;
    cudaGetSymbolAddress(&p, g_rc_ip);    float* rc_ip    = (float*)p;
    cudaGetSymbolAddress(&p, g_H1);       float* H1       = (float*)p;
    cudaGetSymbolAddress(&p, g_H2);       float* H2       = (float*)p;

    __nv_bfloat16 *ipcat_h, *ipcat_l, *conncat_h, *conncat_l;
    __nv_bfloat16 *gik_h, *gik_l, *gir_h, *gir_l, *gck_h, *gck_l, *gcr_h, *gcr_l;
    __nv_bfloat16 *wr1_h, *wr1_l, *wr2_h, *wr2_l;
    cudaGetSymbolAddress(&p, g_ipcat_h);   ipcat_h   = (__nv_bfloat16*)p;
    cudaGetSymbolAddress(&p, g_ipcat_l);   ipcat_l   = (__nv_bfloat16*)p;
    cudaGetSymbolAddress(&p, g_conncat_h); conncat_h = (__nv_bfloat16*)p;
    cudaGetSymbolAddress(&p, g_conncat_l); conncat_l = (__nv_bfloat16*)p;
    cudaGetSymbolAddress(&p, g_gik_h); gik_h = (__nv_bfloat16*)p;
    cudaGetSymbolAddress(&p, g_gik_l); gik_l = (__nv_bfloat16*)p;
    cudaGetSymbolAddress(&p, g_gir_h); gir_h = (__nv_bfloat16*)p;
    cudaGetSymbolAddress(&p, g_gir_l); gir_l = (__nv_bfloat16*)p;
    cudaGetSymbolAddress(&p, g_gck_h); gck_h = (__nv_bfloat16*)p;
    cudaGetSymbolAddress(&p, g_gck_l); gck_l = (__nv_bfloat16*)p;
    cudaGetSymbolAddress(&p, g_gcr_h); gcr_h = (__nv_bfloat16*)p;
    cudaGetSymbolAddress(&p, g_gcr_l); gcr_l = (__nv_bfloat16*)p;
    cudaGetSymbolAddress(&p, g_wr1_h); wr1_h = (__nv_bfloat16*)p;
    cudaGetSymbolAddress(&p, g_wr1_l); wr1_l = (__nv_bfloat16*)p;
    cudaGetSymbolAddress(&p, g_wr2_h); wr2_h = (__nv_bfloat16*)p;
    cudaGetSymbolAddress(&p, g_wr2_l); wr2_l = (__nv_bfloat16*)p;

    // --- merged weight prep (one launch) ---
    prep_all<<<(286720 + 255) / 256, 256>>>(W_m1, W_m2, gik, gir, gck, gcr, Wr1, Wr2);

    // --- segment counts + state init ---
    zero_rc<<<(N_CONN + 255) / 256, 256>>>(rc_conn, rc_ip);
    count2<<<(2 * N_E + 255) / 256, 256>>>(d_i2c, d_c2i, rc_conn, rc_ip);
    recip2<<<(N_CONN + 255) / 256, 256>>>(rc_conn, rc_ip);
    init_states<<<(N_CONN * D128 + 255) / 256, 256>>>(ip, conn, feat);

    const int edge_blocks = (N_E * 32 + 255) / 256;
    const int z4c = N_CONN * 32, z4i = N_IP * 32;

    for (int t = 0; t < T_ITERS; t++) {
        // merged message GEMMs: msg_ip = ip @ [W_XA|W_YB]^T, msg_conn = conn @ [W_XB|W_YA]^T
        launch_g128(ip,   ipcat_h,   ipcat_l,   msg_ip,   N_IP,   256, 256, nullptr, nullptr, 0);
        launch_g128(conn, conncat_h, conncat_l, msg_conn, N_CONN, 256, 256, nullptr, nullptr, 0);

        zero2<<<(z4c + z4i + 255) / 256, 256>>>(agg_conn, z4c, agg_ip, z4i);

        // ip->conn: relu(XA[src_ip] + XB[dst_conn] + b_m1) summed per conn
        edge_msg_kernel<<<edge_blocks, 256>>>(s_i2c, d_i2c, msg_ip, msg_conn, 256,
                                              b_m1, agg_conn, N_E);
        // conn->ip: relu(YA[src_conn] + YB[dst_ip] + b_m2) summed per ip
        edge_msg_kernel<<<edge_blocks, 256>>>(s_c2i, d_c2i, msg_conn + 128, msg_ip + 128, 256,
                                              b_m2, agg_ip, N_E);

        // GRU pre-activations (R11 structure: two plain 384-col GEMMs per node type)
        launch_g128(agg_ip,   gik_h, gik_l, xm_ip, N_IP,   384, 384, gib,       rc_ip,   0);
        launch_g128(ip,       gir_h, gir_l, hm_ip, N_IP,   384, 384, gib + 384, nullptr, 0);
        launch_g128(agg_conn, gck_h, gck_l, xm_c,  N_CONN, 384, 384, gcb,       rc_conn, 0);
        launch_g128(conn,     gcr_h, gcr_l, hm_c,  N_CONN, 384, 384, gcb + 384, nullptr, 0);

        // GRU gate updates (in place)
        gru_gate_kernel<<<(N_IP * 32 + 255) / 256, 256>>>(ip, xm_ip, hm_ip, N_IP);
        gru_gate_kernel<<<(N_CONN * 32 + 255) / 256, 256>>>(conn, xm_c, hm_c, N_CONN);
    }

    // --- readout ---
    launch_g128(conn, wr1_h, wr1_l, H1, N_CONN, 128, 128, br1, nullptr, 1);
    {
        dim3 g((N_CONN + 127) / 128, 1);
        mma_gemm<64><<<g, 256, SMEM64>>>(H1, wr2_h, wr2_l, H2, N_CONN, 64, br2, nullptr, 1);
    }
    readout_kernel<<<(N_CONN + 127) / 128, 128>>>(H2, Wr3, br3, out, N_CONN);
}

// round 14
// speedup vs baseline: 1.2070x; 1.0020x over previous
#include <cuda_runtime.h>
#include <cuda_bf16.h>
#include <cstdint>
#include <cstddef>

#define D128 128
#define NFEAT 10
#define N_IP 20000
#define N_CONN 100000
#define N_E 200000
#define T_ITERS 3

// ---------------- scratch (static device globals; no allocation) ----------------
__device__ float g_ip[N_IP * D128];
__device__ float g_conn[N_CONN * D128];
__device__ float g_msg_ip[N_IP * 256];      // [XA | YB]
__device__ float g_msg_conn[N_CONN * 256];  // [XB | YA]
__device__ float g_agg_conn[N_CONN * D128];
__device__ float g_agg_ip[N_IP * D128];
__device__ float g_xm_ip[N_IP * 384];
__device__ float g_hm_ip[N_IP * 384];
__device__ float g_xm_c[N_CONN * 384];
__device__ float g_hm_c[N_CONN * 384];
__device__ float g_rc_conn[N_CONN];
__device__ float g_rc_ip[N_IP];
__device__ float g_H1[N_CONN * D128];
__device__ float g_H2[N_CONN * 64];

// bf16 hi/lo split, transposed weights [N][128]
__device__ __nv_bfloat16 g_ipcat_h[256 * 128], g_ipcat_l[256 * 128];    // [XA w | YB w]
__device__ __nv_bfloat16 g_conncat_h[256 * 128], g_conncat_l[256 * 128];// [XB w | YA w]
__device__ __nv_bfloat16 g_gik_h[384 * 128], g_gik_l[384 * 128];
__device__ __nv_bfloat16 g_gir_h[384 * 128], g_gir_l[384 * 128];
__device__ __nv_bfloat16 g_gck_h[384 * 128], g_gck_l[384 * 128];
__device__ __nv_bfloat16 g_gcr_h[384 * 128], g_gcr_l[384 * 128];
__device__ __nv_bfloat16 g_wr1_h[128 * 128], g_wr1_l[128 * 128];
__device__ __nv_bfloat16 g_wr2_h[64 * 128],  g_wr2_l[64 * 128];

// ---------------- helpers ----------------
__device__ __forceinline__ uint32_t smem_u32(const void* p) {
    uint32_t a;
    asm("{ .reg .u64 t; cvta.to.shared.u64 t, %1; cvt.u32.u64 %0, t; }" : "=r"(a) : "l"(p));
    return a;
}
__device__ __forceinline__ void ldsm_x4(uint32_t& r0, uint32_t& r1, uint32_t& r2, uint32_t& r3,
                                        uint32_t addr) {
    asm volatile("ldmatrix.sync.aligned.m8n8.x4.shared.b16 {%0,%1,%2,%3}, [%4];"
                 : "=r"(r0), "=r"(r1), "=r"(r2), "=r"(r3) : "r"(addr));
}
__device__ __forceinline__ void mma16816(float* c, const uint32_t* a, const uint32_t* b) {
    asm volatile(
        "mma.sync.aligned.m16n8k16.row.col.f32.bf16.bf16.f32 "
        "{%0,%1,%2,%3}, {%4,%5,%6,%7}, {%8,%9}, {%0,%1,%2,%3};"
        : "+f"(c[0]), "+f"(c[1]), "+f"(c[2]), "+f"(c[3])
        : "r"(a[0]), "r"(a[1]), "r"(a[2]), "r"(a[3]), "r"(b[0]), "r"(b[1]));
}
__device__ __forceinline__ uint32_t pack_bf2(__nv_bfloat16 a, __nv_bfloat16 b) {
    return ((uint32_t)__bfloat16_as_ushort(b) << 16) | (uint32_t)__bfloat16_as_ushort(a);
}

// ---------------- HMMA GEMM (R5/R11/R13-proven, single pass, untouched) ----------------
// C[MxNtot] = act(rowscale(A[Mx128]) @ Wt^T + bias); Wt = [Ntot x 128] bf16 hi/lo.
template <int NTILE>
__global__ __launch_bounds__(256) void mma_gemm(
    const float* __restrict__ A, const __nv_bfloat16* __restrict__ Bh,
    const __nv_bfloat16* __restrict__ Bl, float* __restrict__ C,
    int M, int ldc, const float* __restrict__ bias,
    const float* __restrict__ rscale, int do_relu)
{
    constexpr int WM = (NTILE == 128) ? 64 : 32;
    constexpr int MT = WM / 16;
    constexpr int A_HI = 0, A_LO = 32768, B_HI = 65536;
    constexpr int B_LO = B_HI + NTILE * 256;

    extern __shared__ char smem[];
    const uint32_t sb = smem_u32(smem);
    const int tid = threadIdx.x, wid = tid >> 5, lane = tid & 31;
    const int m0 = blockIdx.x * 128;
    const int col0 = blockIdx.y * NTILE;
    int wm, wn;
    if (NTILE == 128) { wm = wid & 1; wn = wid >> 1; }
    else              { wm = wid & 3; wn = wid >> 2; }

#pragma unroll
    for (int i = 0; i < 8; i++) {
        int idx = tid + i * 256;
        int r = idx >> 4, kc = idx & 15;
        int gr = m0 + r;
        float4 v0 = make_float4(0.f, 0.f, 0.f, 0.f), v1 = v0;
        if (gr < M) {
            const float* ap = A + (size_t)gr * 128 + kc * 8;
            v0 = *(const float4*)ap;
            v1 = *(const float4*)(ap + 4);
            if (rscale) {
                float s = rscale[gr];
                v0.x *= s; v0.y *= s; v0.z *= s; v0.w *= s;
                v1.x *= s; v1.y *= s; v1.z *= s; v1.w *= s;
            }
        }
        float f[8] = {v0.x, v0.y, v0.z, v0.w, v1.x, v1.y, v1.z, v1.w};
        uint32_t hw[4], lw[4];
#pragma unroll
        for (int j = 0; j < 4; j++) {
            __nv_bfloat16 h0 = __float2bfloat16(f[2 * j]);
            __nv_bfloat16 h1 = __float2bfloat16(f[2 * j + 1]);
            __nv_bfloat16 l0 = __float2bfloat16(f[2 * j] - __bfloat162float(h0));
            __nv_bfloat16 l1 = __float2bfloat16(f[2 * j + 1] - __bfloat162float(h1));
            hw[j] = pack_bf2(h0, h1);
            lw[j] = pack_bf2(l0, l1);
        }
        uint32_t sw = (uint32_t)(r * 256 + ((kc ^ (r & 7)) << 4));
        *(uint4*)(smem + A_HI + sw) = make_uint4(hw[0], hw[1], hw[2], hw[3]);
        *(uint4*)(smem + A_LO + sw) = make_uint4(lw[0], lw[1], lw[2], lw[3]);
    }
#pragma unroll
    for (int i = 0; i < NTILE / 16; i++) {
        int idx = tid + i * 256;
        int r = idx >> 4, kc = idx & 15;
        uint32_t sw = (uint32_t)(r * 256 + ((kc ^ (r & 7)) << 4));
        *(uint4*)(smem + B_HI + sw) = ((const uint4*)(Bh + (size_t)(col0 + r) * 128))[kc];
        *(uint4*)(smem + B_LO + sw) = ((const uint4*)(Bl + (size_t)(col0 + r) * 128))[kc];
    }
    __syncthreads();

    float acc[MT][4][4];
#pragma unroll
    for (int mt = 0; mt < MT; mt++)
#pragma unroll
        for (int nt = 0; nt < 4; nt++)
#pragma unroll
            for (int j = 0; j < 4; j++) acc[mt][nt][j] = 0.f;

    const int rA = ((lane >> 3) & 1) * 8 + (lane & 7);
    const int cA = lane >> 4;
    const int rB = ((lane >> 4) << 3) + (lane & 7);
    const int cB = (lane >> 3) & 1;

#pragma unroll
    for (int ks = 0; ks < 8; ks++) {
        const int kc0 = ks * 2;
        uint32_t ah[MT][4], al[MT][4], bh[4][2], bl[4][2];
#pragma unroll
        for (int mt = 0; mt < MT; mt++) {
            int row = wm * WM + mt * 16 + rA;
            uint32_t ad = sb + A_HI + row * 256 + (((kc0 + cA) ^ (row & 7)) << 4);
            ldsm_x4(ah[mt][0], ah[mt][1], ah[mt][2], ah[mt][3], ad);
            ldsm_x4(al[mt][0], al[mt][1], al[mt][2], al[mt][3], ad + (A_LO - A_HI));
        }
#pragma unroll
        for (int p = 0; p < 2; p++) {
            int row = wn * 32 + p * 16 + rB;
            uint32_t bd = sb + B_HI + row * 256 + (((kc0 + cB) ^ (row & 7)) << 4);
            uint32_t r0, r1, r2, r3;
            ldsm_x4(r0, r1, r2, r3, bd);
            bh[p * 2][0] = r0; bh[p * 2][1] = r1; bh[p * 2 + 1][0] = r2; bh[p * 2 + 1][1] = r3;
            ldsm_x4(r0, r1, r2, r3, bd + (B_LO - B_HI));
            bl[p * 2][0] = r0; bl[p * 2][1] = r1; bl[p * 2 + 1][0] = r2; bl[p * 2 + 1][1] = r3;
        }
#pragma unroll
        for (int mt = 0; mt < MT; mt++)
#pragma unroll
            for (int nt = 0; nt < 4; nt++) {
                mma16816(acc[mt][nt], ah[mt], bh[nt]);
                mma16816(acc[mt][nt], ah[mt], bl[nt]);
                mma16816(acc[mt][nt], al[mt], bh[nt]);
            }
    }

    const int rowg = lane >> 2, colg = (lane & 3) * 2;
#pragma unroll
    for (int mt = 0; mt < MT; mt++) {
#pragma unroll
        for (int nt = 0; nt < 4; nt++) {
            int gc = col0 + wn * 32 + nt * 8 + colg;
            float bx = 0.f, by = 0.f;
            if (bias) { bx = __ldg(bias + gc); by = __ldg(bias + gc + 1); }
#pragma unroll
            for (int h = 0; h < 2; h++) {
                int gr = m0 + wm * WM + mt * 16 + h * 8 + rowg;
                if (gr < M) {
                    float x = acc[mt][nt][h * 2 + 0] + bx;
                    float y = acc[mt][nt][h * 2 + 1] + by;
                    if (do_relu) { x = fmaxf(x, 0.f); y = fmaxf(y, 0.f); }
                    float2 o; o.x = x; o.y = y;
                    *(float2*)(C + (size_t)gr * ldc + gc) = o;
                }
            }
        }
    }
}

// ---------------- merged weight prep: transposes + bf16 hi/lo split, one launch ----------
__global__ void prep_all(const float* __restrict__ W_m1, const float* __restrict__ W_m2,
                         const float* __restrict__ gik, const float* __restrict__ gir,
                         const float* __restrict__ gck, const float* __restrict__ gcr,
                         const float* __restrict__ Wr1, const float* __restrict__ Wr2)
{
    int idx = blockIdx.x * blockDim.x + threadIdx.x;
    const float* src;
    __nv_bfloat16 *hi, *lo;
    int ldN, l;
    if (idx < 65536) {
        int j = idx >> 14;
        l = idx & 16383;
        ldN = 128;
        if (j == 0)      { src = W_m1;          hi = g_ipcat_h;           lo = g_ipcat_l; }
        else if (j == 1) { src = W_m2 + 16384;  hi = g_ipcat_h + 16384;   lo = g_ipcat_l + 16384; }
        else if (j == 2) { src = W_m1 + 16384;  hi = g_conncat_h;         lo = g_conncat_l; }
        else             { src = W_m2;          hi = g_conncat_h + 16384; lo = g_conncat_l + 16384; }
    } else if (idx < 262144) {
        int t = idx - 65536;
        int j = t / 49152;
        l = t % 49152;
        ldN = 384;
        if (j == 0)      { src = gik; hi = g_gik_h; lo = g_gik_l; }
        else if (j == 1) { src = gir; hi = g_gir_h; lo = g_gir_l; }
        else if (j == 2) { src = gck; hi = g_gck_h; lo = g_gck_l; }
        else             { src = gcr; hi = g_gcr_h; lo = g_gcr_l; }
    } else if (idx < 278528) {
        l = idx - 262144;
        ldN = 128;
        src = Wr1; hi = g_wr1_h; lo = g_wr1_l;
    } else if (idx < 286720) {
        l = idx - 278528;
        ldN = 64;
        src = Wr2; hi = g_wr2_h; lo = g_wr2_l;
    } else {
        return;
    }
    int n = l >> 7, k = l & 127;
    float x = src[(size_t)k * ldN + n];
    __nv_bfloat16 h = __float2bfloat16(x);
    hi[l] = h;
    lo[l] = __float2bfloat16(x - __bfloat162float(h));
}

// ---------------- small utility kernels ----------------
__global__ void init_states(float* __restrict__ ip, float* __restrict__ conn,
                            const float* __restrict__ feat) {
    int i = blockIdx.x * blockDim.x + threadIdx.x;
    if (i < N_CONN * D128) {
        int r = i >> 7, c = i & 127;
        conn[i] = (c < NFEAT) ? feat[r * NFEAT + c] : 0.f;
        if (i < N_IP * D128) ip[i] = 1.f;
    }
}
__global__ void zero_rc(float* __restrict__ c1, float* __restrict__ c2) {
    int i = blockIdx.x * blockDim.x + threadIdx.x;
    if (i < N_CONN) c1[i] = 0.f;
    if (i < N_IP) c2[i] = 0.f;
}
__global__ void count2(const int* __restrict__ d1, const int* __restrict__ d2,
                       float* __restrict__ c1, float* __restrict__ c2) {
    int i = blockIdx.x * blockDim.x + threadIdx.x;
    if (i < N_E) atomicAdd(c1 + d1[i], 1.f);
    else if (i < 2 * N_E) atomicAdd(c2 + d2[i - N_E], 1.f);
}
__global__ void recip2(float* __restrict__ c1, float* __restrict__ c2) {
    int i = blockIdx.x * blockDim.x + threadIdx.x;
    if (i < N_CONN) c1[i] = 1.f / fmaxf(c1[i], 1.f);
    if (i < N_IP) c2[i] = 1.f / fmaxf(c2[i], 1.f);
}
__global__ void zero2(float* __restrict__ a, int n4a, float* __restrict__ b, int n4b) {
    int i = blockIdx.x * blockDim.x + threadIdx.x;
    if (i < n4a) *(float4*)(a + (size_t)i * 4) = make_float4(0.f, 0.f, 0.f, 0.f);
    else if (i < n4a + n4b)
        *(float4*)(b + (size_t)(i - n4a) * 4) = make_float4(0.f, 0.f, 0.f, 0.f);
}

// ---------------- merged edge message + scatter (both directions, red.v4) ----------------
__global__ void edge_msg2x(
    const int* __restrict__ s0, const int* __restrict__ d0,
    const int* __restrict__ s1, const int* __restrict__ d1,
    const float* __restrict__ XS0, const float* __restrict__ XD0,
    const float* __restrict__ XS1, const float* __restrict__ XD1,
    const float* __restrict__ b0, const float* __restrict__ b1,
    float* __restrict__ out0, float* __restrict__ out1)
{
    int gw = (blockIdx.x * blockDim.x + threadIdx.x) >> 5;
    int lane = threadIdx.x & 31;
    const int* srcp;
    const int* dstp;
    const float *XS, *XD, *bias;
    float* outp;
    if (gw < N_E) {
        srcp = s0; dstp = d0; XS = XS0; XD = XD0; bias = b0; outp = out0;
    } else {
        gw -= N_E;
        if (gw >= N_E) return;
        srcp = s1; dstp = d1; XS = XS1; XD = XD1; bias = b1; outp = out1;
    }
    int s = __ldg(srcp + gw);
    int d = __ldg(dstp + gw);
    int c = lane << 2;
    float4 a = *(const float4*)(XS + (size_t)s * 256 + c);
    float4 b = *(const float4*)(XD + (size_t)d * 256 + c);
    float4 bb = *(const float4*)(bias + c);
    float4 m;
    m.x = fmaxf(a.x + b.x + bb.x, 0.f);
    m.y = fmaxf(a.y + b.y + bb.y, 0.f);
    m.z = fmaxf(a.z + b.z + bb.z, 0.f);
    m.w = fmaxf(a.w + b.w + bb.w, 0.f);
    float* p = outp + (size_t)d * 128 + c;
    asm volatile("red.global.add.v4.f32 [%0], {%1, %2, %3, %4};"
                 :: "l"(p), "f"(m.x), "f"(m.y), "f"(m.z), "f"(m.w) : "memory");
}

// ---------------- merged GRU gate (ip + conn) + agg zero-fill tail ----------------
__device__ __forceinline__ float gru1(float xz, float hz, float xr, float hr,
                                      float xh, float hh, float h) {
    float z = 1.f / (1.f + expf(-(xz + hz)));
    float r = 1.f / (1.f + expf(-(xr + hr)));
    float c = tanhf(xh + r * hh);
    return z * h + (1.f - z) * c;
}
// idx layout: [0, G_IP) ip gate; [G_IP, G_ALL) conn gate;
//             [G_ALL, G_ALL+Z_IP) zero agg_ip (float4); [.., +Z_CONN) zero agg_conn.
#define G_IP   (N_IP * 32)
#define G_ALL  ((N_IP + N_CONN) * 32)
#define Z_IP   (N_IP * 32)
#define Z_CONN (N_CONN * 32)
__global__ void gru_gate2x(float* __restrict__ h0, const float* __restrict__ xm0,
                           const float* __restrict__ hm0,
                           float* __restrict__ h1, const float* __restrict__ xm1,
                           const float* __restrict__ hm1,
                           float* __restrict__ za, float* __restrict__ zb)
{
    int idx = blockIdx.x * blockDim.x + threadIdx.x;
    if (idx >= G_ALL) {
        int z = idx - G_ALL;
        if (z < Z_IP) {
            *(float4*)(za + (size_t)z * 4) = make_float4(0.f, 0.f, 0.f, 0.f);
        } else {
            z -= Z_IP;
            if (z < Z_CONN)
                *(float4*)(zb + (size_t)z * 4) = make_float4(0.f, 0.f, 0.f, 0.f);
        }
        return;
    }
    float* h;
    const float *xm, *hm;
    if (idx < G_IP) {
        h = h0; xm = xm0; hm = hm0;
    } else {
        idx -= G_IP;
        h = h1; xm = xm1; hm = hm1;
    }
    int row = idx >> 5;
    int c = (idx & 31) << 2;
    const float* x = xm + (size_t)row * 384;
    const float* hh = hm + (size_t)row * 384;
    float4 xz = *(const float4*)(x + c);
    float4 xr = *(const float4*)(x + 128 + c);
    float4 xh = *(const float4*)(x + 256 + c);
    float4 hz = *(const float4*)(hh + c);
    float4 hr = *(const float4*)(hh + 128 + c);
    float4 hc = *(const float4*)(hh + 256 + c);
    float* hp = h + (size_t)row * 128 + c;
    float4 hv = *(const float4*)hp;
    float4 o;
    o.x = gru1(xz.x, hz.x, xr.x, hr.x, xh.x, hc.x, hv.x);
    o.y = gru1(xz.y, hz.y, xr.y, hr.y, xh.y, hc.y, hv.y);
    o.z = gru1(xz.z, hz.z, xr.z, hr.z, xh.z, hc.z, hv.z);
    o.w = gru1(xz.w, hz.w, xr.w, hr.w, xh.w, hc.w, hv.w);
    *(float4*)hp = o;
}

// ---------------- readout tail ----------------
__global__ void readout_kernel(const float* __restrict__ H2, const float* __restrict__ W3,
                               const float* __restrict__ b3, float* __restrict__ out, int M)
{
    __shared__ float w[64 * 15];
    __shared__ float bb[15];
    for (int i = threadIdx.x; i < 64 * 15; i += blockDim.x) w[i] = W3[i];
    if (threadIdx.x < 15) bb[threadIdx.x] = b3[threadIdx.x];
    __syncthreads();
    int row = blockIdx.x * blockDim.x + threadIdx.x;
    if (row >= M) return;
    float acc[15];
#pragma unroll
    for (int j = 0; j < 15; j++) acc[j] = bb[j];
    const float* hrow = H2 + (size_t)row * 64;
#pragma unroll 16
    for (int k = 0; k < 64; k++) {
        float hv = __ldg(hrow + k);
#pragma unroll
        for (int j = 0; j < 15; j++) acc[j] += hv * w[k * 15 + j];
    }
    float mx = acc[0];
#pragma unroll
    for (int j = 1; j < 15; j++) mx = fmaxf(mx, acc[j]);
    float sum = 0.f;
#pragma unroll
    for (int j = 0; j < 15; j++) { acc[j] = expf(acc[j] - mx); sum += acc[j]; }
    float inv = 1.f / sum;
    float* op = out + (size_t)row * 15;
#pragma unroll
    for (int j = 0; j < 15; j++) op[j] = acc[j] * inv;
}

// ---------------- host side ----------------
static const int SMEM128 = 65536 + 128 * 512;  // 131072
static const int SMEM64  = 65536 + 64 * 512;   // 98304

static inline void launch_g128(const float* A, const __nv_bfloat16* Bh, const __nv_bfloat16* Bl,
                               float* C, int M, int Ntot, int ldc, const float* bias,
                               const float* rs, int relu) {
    dim3 g((M + 127) / 128, Ntot / 128);
    mma_gemm<128><<<g, 256, SMEM128>>>(A, Bh, Bl, C, M, ldc, bias, rs, relu);
}

extern "C" void kernel_launch(void* const* d_in, const int* in_sizes, int n_in,
                              void* d_out, int out_size)
{
    const float* feat  = (const float*)d_in[0];
    const int*   s_i2c = (const int*)d_in[1];
    const int*   d_i2c = (const int*)d_in[2];
    const int*   s_c2i = (const int*)d_in[3];
    const int*   d_c2i = (const int*)d_in[4];
    const float* W_m1  = (const float*)d_in[5];
    const float* b_m1  = (const float*)d_in[6];
    const float* W_m2  = (const float*)d_in[7];
    const float* b_m2  = (const float*)d_in[8];
    const float* gik   = (const float*)d_in[9];
    const float* gir   = (const float*)d_in[10];
    const float* gib   = (const float*)d_in[11];
    const float* gck   = (const float*)d_in[12];
    const float* gcr   = (const float*)d_in[13];
    const float* gcb   = (const float*)d_in[14];
    const float* Wr1   = (const float*)d_in[15];
    const float* br1   = (const float*)d_in[16];
    const float* Wr2   = (const float*)d_in[17];
    const float* br2   = (const float*)d_in[18];
    const float* Wr3   = (const float*)d_in[19];
    const float* br3   = (const float*)d_in[20];
    float* out = (float*)d_out;

    cudaFuncSetAttribute(mma_gemm<128>, cudaFuncAttributeMaxDynamicSharedMemorySize, SMEM128);
    cudaFuncSetAttribute(mma_gemm<64>,  cudaFuncAttributeMaxDynamicSharedMemorySize, SMEM64);

    void* p;
    cudaGetSymbolAddress(&p, g_ip);       float* ip       = (float*)p;
    cudaGetSymbolAddress(&p, g_conn);     float* conn     = (float*)p;
    cudaGetSymbolAddress(&p, g_msg_ip);   float* msg_ip   = (float*)p;
    cudaGetSymbolAddress(&p, g_msg_conn); float* msg_conn = (float*)p;
    cudaGetSymbolAddress(&p, g_agg_conn); float* agg_conn = (float*)p;
    cudaGetSymbolAddress(&p, g_agg_ip);   float* agg_ip   = (float*)p;
    cudaGetSymbolAddress(&p, g_xm_ip);    float* xm_ip    = (float*)p;
    cudaGetSymbolAddress(&p, g_hm_ip);    float* hm_ip    = (float*)p;
    cudaGetSymbolAddress(&p, g_xm_c);     float* xm_c     = (float*)p;
    cudaGetSymbolAddress(&p, g_hm_c);     float* hm_c     = (float*)p;
    cudaGetSymbolAddress(&p, g_rc_conn);  float* rc_conn  = (float*)p;
    cudaGetSymbolAddress(&p, g_rc_ip);    float* rc_ip    = (float*)p;
    cudaGetSymbolAddress(&p, g_H1);       float* H1       = (float*)p;
    cudaGetSymbolAddress(&p, g_H2);       float* H2       = (float*)p;

    __nv_bfloat16 *ipcat_h, *ipcat_l, *conncat_h, *conncat_l;
    __nv_bfloat16 *gik_h, *gik_l, *gir_h, *gir_l, *gck_h, *gck_l, *gcr_h, *gcr_l;
    __nv_bfloat16 *wr1_h, *wr1_l, *wr2_h, *wr2_l;
    cudaGetSymbolAddress(&p, g_ipcat_h);   ipcat_h   = (__nv_bfloat16*)p;
    cudaGetSymbolAddress(&p, g_ipcat_l);   ipcat_l   = (__nv_bfloat16*)p;
    cudaGetSymbolAddress(&p, g_conncat_h); conncat_h = (__nv_bfloat16*)p;
    cudaGetSymbolAddress(&p, g_conncat_l); conncat_l = (__nv_bfloat16*)p;
    cudaGetSymbolAddress(&p, g_gik_h); gik_h = (__nv_bfloat16*)p;
    cudaGetSymbolAddress(&p, g_gik_l); gik_l = (__nv_bfloat16*)p;
    cudaGetSymbolAddress(&p, g_gir_h); gir_h = (__nv_bfloat16*)p;
    cudaGetSymbolAddress(&p, g_gir_l); gir_l = (__nv_bfloat16*)p;
    cudaGetSymbolAddress(&p, g_gck_h); gck_h = (__nv_bfloat16*)p;
    cudaGetSymbolAddress(&p, g_gck_l); gck_l = (__nv_bfloat16*)p;
    cudaGetSymbolAddress(&p, g_gcr_h); gcr_h = (__nv_bfloat16*)p;
    cudaGetSymbolAddress(&p, g_gcr_l); gcr_l = (__nv_bfloat16*)p;
    cudaGetSymbolAddress(&p, g_wr1_h); wr1_h = (__nv_bfloat16*)p;
    cudaGetSymbolAddress(&p, g_wr1_l); wr1_l = (__nv_bfloat16*)p;
    cudaGetSymbolAddress(&p, g_wr2_h); wr2_h = (__nv_bfloat16*)p;
    cudaGetSymbolAddress(&p, g_wr2_l); wr2_l = (__nv_bfloat16*)p;

    // --- merged weight prep (one launch) ---
    prep_all<<<(286720 + 255) / 256, 256>>>(W_m1, W_m2, gik, gir, gck, gcr, Wr1, Wr2);

    // --- segment counts + state init + initial agg zero ---
    zero_rc<<<(N_CONN + 255) / 256, 256>>>(rc_conn, rc_ip);
    count2<<<(2 * N_E + 255) / 256, 256>>>(d_i2c, d_c2i, rc_conn, rc_ip);
    recip2<<<(N_CONN + 255) / 256, 256>>>(rc_conn, rc_ip);
    init_states<<<(N_CONN * D128 + 255) / 256, 256>>>(ip, conn, feat);
    zero2<<<(Z_IP + Z_CONN + 255) / 256, 256>>>(agg_ip, Z_IP, agg_conn, Z_CONN);

    const int edge_blocks = (2 * N_E * 32 + 255) / 256;
    const int gate_blocks = (G_ALL + Z_IP + Z_CONN + 255) / 256;

    for (int t = 0; t < T_ITERS; t++) {
        // merged message GEMMs
        launch_g128(ip,   ipcat_h,   ipcat_l,   msg_ip,   N_IP,   256, 256, nullptr, nullptr, 0);
        launch_g128(conn, conncat_h, conncat_l, msg_conn, N_CONN, 256, 256, nullptr, nullptr, 0);

        // merged edge kernels (both directions, vectorized reductions)
        edge_msg2x<<<edge_blocks, 256>>>(s_i2c, d_i2c, s_c2i, d_c2i,
                                         msg_ip, msg_conn, msg_conn + 128, msg_ip + 128,
                                         b_m1, b_m2, agg_conn, agg_ip);

        // GRU pre-activations (proven single-pass GEMMs)
        launch_g128(agg_ip,   gik_h, gik_l, xm_ip, N_IP,   384, 384, gib,       rc_ip,   0);
        launch_g128(ip,       gir_h, gir_l, hm_ip, N_IP,   384, 384, gib + 384, nullptr, 0);
        launch_g128(agg_conn, gck_h, gck_l, xm_c,  N_CONN, 384, 384, gcb,       rc_conn, 0);
        launch_g128(conn,     gcr_h, gcr_l, hm_c,  N_CONN, 384, 384, gcb + 384, nullptr, 0);

        // merged gate update (in place) + zero agg for next iteration
        gru_gate2x<<<gate_blocks, 256>>>(ip, xm_ip, hm_ip, conn, xm_c, hm_c,
                                         agg_ip, agg_conn);
    }

    // --- readout ---
    launch_g128(conn, wr1_h, wr1_l, H1, N_CONN, 128, 128, br1, nullptr, 1);
    {
        dim3 g((N_CONN + 127) / 128, 1);
        mma_gemm<64><<<g, 256, SMEM64>>>(H1, wr2_h, wr2_l, H2, N_CONN, 64, br2, nullptr, 1);
    }
    readout_kernel<<<(N_CONN + 127) / 128, 128>>>(H2, Wr3, br3, out, N_CONN);
}

// round 15
// speedup vs baseline: 1.4214x; 1.1776x over previous
#include <cuda_runtime.h>
#include <cuda_bf16.h>
#include <cstdint>
#include <cstddef>

#define D128 128
#define NFEAT 10
#define N_IP 20000
#define N_CONN 100000
#define N_E 200000
#define T_ITERS 3

// ---------------- scratch (static device globals; no allocation) ----------------
__device__ float g_ip[N_IP * D128];
__device__ float g_conn[N_CONN * D128];
__device__ float g_msg_ip[N_IP * 256];      // [XA | YB]
__device__ float g_msg_conn[N_CONN * 256];  // [XB | YA]
__device__ float g_agg_conn[N_CONN * D128];
__device__ float g_agg_ip[N_IP * D128];
__device__ float g_xm_ip[N_IP * 384];
__device__ float g_hm_ip[N_IP * 384];
__device__ float g_xm_c[N_CONN * 384];
__device__ float g_hm_c[N_CONN * 384];
__device__ float g_rc_conn[N_CONN];
__device__ float g_rc_ip[N_IP];
__device__ float g_H1[N_CONN * D128];
__device__ float g_H2[N_CONN * 64];

// bf16 hi/lo split, transposed weights [N][128]
__device__ __nv_bfloat16 g_ipcat_h[256 * 128], g_ipcat_l[256 * 128];    // [XA w | YB w]
__device__ __nv_bfloat16 g_conncat_h[256 * 128], g_conncat_l[256 * 128];// [XB w | YA w]
__device__ __nv_bfloat16 g_gik_h[384 * 128], g_gik_l[384 * 128];
__device__ __nv_bfloat16 g_gir_h[384 * 128], g_gir_l[384 * 128];
__device__ __nv_bfloat16 g_gck_h[384 * 128], g_gck_l[384 * 128];
__device__ __nv_bfloat16 g_gcr_h[384 * 128], g_gcr_l[384 * 128];
__device__ __nv_bfloat16 g_wr1_h[128 * 128], g_wr1_l[128 * 128];
__device__ __nv_bfloat16 g_wr2_h[64 * 128],  g_wr2_l[64 * 128];

// ---------------- helpers ----------------
__device__ __forceinline__ uint32_t smem_u32(const void* p) {
    uint32_t a;
    asm("{ .reg .u64 t; cvta.to.shared.u64 t, %1; cvt.u32.u64 %0, t; }" : "=r"(a) : "l"(p));
    return a;
}
__device__ __forceinline__ void ldsm_x4(uint32_t& r0, uint32_t& r1, uint32_t& r2, uint32_t& r3,
                                        uint32_t addr) {
    asm volatile("ldmatrix.sync.aligned.m8n8.x4.shared.b16 {%0,%1,%2,%3}, [%4];"
                 : "=r"(r0), "=r"(r1), "=r"(r2), "=r"(r3) : "r"(addr));
}
__device__ __forceinline__ void mma16816(float* c, const uint32_t* a, const uint32_t* b) {
    asm volatile(
        "mma.sync.aligned.m16n8k16.row.col.f32.bf16.bf16.f32 "
        "{%0,%1,%2,%3}, {%4,%5,%6,%7}, {%8,%9}, {%0,%1,%2,%3};"
        : "+f"(c[0]), "+f"(c[1]), "+f"(c[2]), "+f"(c[3])
        : "r"(a[0]), "r"(a[1]), "r"(a[2]), "r"(a[3]), "r"(b[0]), "r"(b[1]));
}
__device__ __forceinline__ uint32_t pack_bf2(__nv_bfloat16 a, __nv_bfloat16 b) {
    return ((uint32_t)__bfloat16_as_ushort(b) << 16) | (uint32_t)__bfloat16_as_ushort(a);
}

// ---------------- HMMA GEMM (proven body; BM = block rows as template param) ----------------
// C[MxNtot] = act(rowscale(A[Mx128]) @ Wt^T + bias); Wt = [Ntot x 128] bf16 hi/lo.
// BM=64 -> 96KB smem -> 2 CTAs/SM; BM=128 -> original 131KB config.
template <int NTILE, int BM>
__global__ __launch_bounds__(256) void mma_gemm(
    const float* __restrict__ A, const __nv_bfloat16* __restrict__ Bh,
    const __nv_bfloat16* __restrict__ Bl, float* __restrict__ C,
    int M, int ldc, const float* __restrict__ bias,
    const float* __restrict__ rscale, int do_relu)
{
    constexpr int WM = (NTILE == 128) ? (BM / 2) : (BM / 4);
    constexpr int MT = WM / 16;
    constexpr int A_HI = 0;
    constexpr int A_LO = BM * 256;
    constexpr int B_HI = 2 * BM * 256;
    constexpr int B_LO = B_HI + NTILE * 256;

    extern __shared__ char smem[];
    const uint32_t sb = smem_u32(smem);
    const int tid = threadIdx.x, wid = tid >> 5, lane = tid & 31;
    const int m0 = blockIdx.x * BM;
    const int col0 = blockIdx.y * NTILE;
    int wm, wn;
    if (NTILE == 128) { wm = wid & 1; wn = wid >> 1; }
    else              { wm = wid & 3; wn = wid >> 2; }

#pragma unroll
    for (int i = 0; i < BM / 16; i++) {
        int idx = tid + i * 256;
        int r = idx >> 4, kc = idx & 15;
        int gr = m0 + r;
        float4 v0 = make_float4(0.f, 0.f, 0.f, 0.f), v1 = v0;
        if (gr < M) {
            const float* ap = A + (size_t)gr * 128 + kc * 8;
            v0 = *(const float4*)ap;
            v1 = *(const float4*)(ap + 4);
            if (rscale) {
                float s = rscale[gr];
                v0.x *= s; v0.y *= s; v0.z *= s; v0.w *= s;
                v1.x *= s; v1.y *= s; v1.z *= s; v1.w *= s;
            }
        }
        float f[8] = {v0.x, v0.y, v0.z, v0.w, v1.x, v1.y, v1.z, v1.w};
        uint32_t hw[4], lw[4];
#pragma unroll
        for (int j = 0; j < 4; j++) {
            __nv_bfloat16 h0 = __float2bfloat16(f[2 * j]);
            __nv_bfloat16 h1 = __float2bfloat16(f[2 * j + 1]);
            __nv_bfloat16 l0 = __float2bfloat16(f[2 * j] - __bfloat162float(h0));
            __nv_bfloat16 l1 = __float2bfloat16(f[2 * j + 1] - __bfloat162float(h1));
            hw[j] = pack_bf2(h0, h1);
            lw[j] = pack_bf2(l0, l1);
        }
        uint32_t sw = (uint32_t)(r * 256 + ((kc ^ (r & 7)) << 4));
        *(uint4*)(smem + A_HI + sw) = make_uint4(hw[0], hw[1], hw[2], hw[3]);
        *(uint4*)(smem + A_LO + sw) = make_uint4(lw[0], lw[1], lw[2], lw[3]);
    }
#pragma unroll
    for (int i = 0; i < NTILE / 16; i++) {
        int idx = tid + i * 256;
        int r = idx >> 4, kc = idx & 15;
        uint32_t sw = (uint32_t)(r * 256 + ((kc ^ (r & 7)) << 4));
        *(uint4*)(smem + B_HI + sw) = ((const uint4*)(Bh + (size_t)(col0 + r) * 128))[kc];
        *(uint4*)(smem + B_LO + sw) = ((const uint4*)(Bl + (size_t)(col0 + r) * 128))[kc];
    }
    __syncthreads();

    float acc[MT][4][4];
#pragma unroll
    for (int mt = 0; mt < MT; mt++)
#pragma unroll
        for (int nt = 0; nt < 4; nt++)
#pragma unroll
            for (int j = 0; j < 4; j++) acc[mt][nt][j] = 0.f;

    const int rA = ((lane >> 3) & 1) * 8 + (lane & 7);
    const int cA = lane >> 4;
    const int rB = ((lane >> 4) << 3) + (lane & 7);
    const int cB = (lane >> 3) & 1;

#pragma unroll
    for (int ks = 0; ks < 8; ks++) {
        const int kc0 = ks * 2;
        uint32_t ah[MT][4], al[MT][4], bh[4][2], bl[4][2];
#pragma unroll
        for (int mt = 0; mt < MT; mt++) {
            int row = wm * WM + mt * 16 + rA;
            uint32_t ad = sb + A_HI + row * 256 + (((kc0 + cA) ^ (row & 7)) << 4);
            ldsm_x4(ah[mt][0], ah[mt][1], ah[mt][2], ah[mt][3], ad);
            ldsm_x4(al[mt][0], al[mt][1], al[mt][2], al[mt][3], ad + (A_LO - A_HI));
        }
#pragma unroll
        for (int p = 0; p < 2; p++) {
            int row = wn * 32 + p * 16 + rB;
            uint32_t bd = sb + B_HI + row * 256 + (((kc0 + cB) ^ (row & 7)) << 4);
            uint32_t r0, r1, r2, r3;
            ldsm_x4(r0, r1, r2, r3, bd);
            bh[p * 2][0] = r0; bh[p * 2][1] = r1; bh[p * 2 + 1][0] = r2; bh[p * 2 + 1][1] = r3;
            ldsm_x4(r0, r1, r2, r3, bd + (B_LO - B_HI));
            bl[p * 2][0] = r0; bl[p * 2][1] = r1; bl[p * 2 + 1][0] = r2; bl[p * 2 + 1][1] = r3;
        }
#pragma unroll
        for (int mt = 0; mt < MT; mt++)
#pragma unroll
            for (int nt = 0; nt < 4; nt++) {
                mma16816(acc[mt][nt], ah[mt], bh[nt]);
                mma16816(acc[mt][nt], ah[mt], bl[nt]);
                mma16816(acc[mt][nt], al[mt], bh[nt]);
            }
    }

    const int rowg = lane >> 2, colg = (lane & 3) * 2;
#pragma unroll
    for (int mt = 0; mt < MT; mt++) {
#pragma unroll
        for (int nt = 0; nt < 4; nt++) {
            int gc = col0 + wn * 32 + nt * 8 + colg;
            float bx = 0.f, by = 0.f;
            if (bias) { bx = __ldg(bias + gc); by = __ldg(bias + gc + 1); }
#pragma unroll
            for (int h = 0; h < 2; h++) {
                int gr = m0 + wm * WM + mt * 16 + h * 8 + rowg;
                if (gr < M) {
                    float x = acc[mt][nt][h * 2 + 0] + bx;
                    float y = acc[mt][nt][h * 2 + 1] + by;
                    if (do_relu) { x = fmaxf(x, 0.f); y = fmaxf(y, 0.f); }
                    float2 o; o.x = x; o.y = y;
                    *(float2*)(C + (size_t)gr * ldc + gc) = o;
                }
            }
        }
    }
}

// ---------------- merged weight prep: transposes + bf16 hi/lo split, one launch ----------
__global__ void prep_all(const float* __restrict__ W_m1, const float* __restrict__ W_m2,
                         const float* __restrict__ gik, const float* __restrict__ gir,
                         const float* __restrict__ gck, const float* __restrict__ gcr,
                         const float* __restrict__ Wr1, const float* __restrict__ Wr2)
{
    int idx = blockIdx.x * blockDim.x + threadIdx.x;
    const float* src;
    __nv_bfloat16 *hi, *lo;
    int ldN, l;
    if (idx < 65536) {
        int j = idx >> 14;
        l = idx & 16383;
        ldN = 128;
        if (j == 0)      { src = W_m1;          hi = g_ipcat_h;           lo = g_ipcat_l; }
        else if (j == 1) { src = W_m2 + 16384;  hi = g_ipcat_h + 16384;   lo = g_ipcat_l + 16384; }
        else if (j == 2) { src = W_m1 + 16384;  hi = g_conncat_h;         lo = g_conncat_l; }
        else             { src = W_m2;          hi = g_conncat_h + 16384; lo = g_conncat_l + 16384; }
    } else if (idx < 262144) {
        int t = idx - 65536;
        int j = t / 49152;
        l = t % 49152;
        ldN = 384;
        if (j == 0)      { src = gik; hi = g_gik_h; lo = g_gik_l; }
        else if (j == 1) { src = gir; hi = g_gir_h; lo = g_gir_l; }
        else if (j == 2) { src = gck; hi = g_gck_h; lo = g_gck_l; }
        else             { src = gcr; hi = g_gcr_h; lo = g_gcr_l; }
    } else if (idx < 278528) {
        l = idx - 262144;
        ldN = 128;
        src = Wr1; hi = g_wr1_h; lo = g_wr1_l;
    } else if (idx < 286720) {
        l = idx - 278528;
        ldN = 64;
        src = Wr2; hi = g_wr2_h; lo = g_wr2_l;
    } else {
        return;
    }
    int n = l >> 7, k = l & 127;
    float x = src[(size_t)k * ldN + n];
    __nv_bfloat16 h = __float2bfloat16(x);
    hi[l] = h;
    lo[l] = __float2bfloat16(x - __bfloat162float(h));
}

// ---------------- small utility kernels ----------------
__global__ void init_states(float* __restrict__ ip, float* __restrict__ conn,
                            const float* __restrict__ feat) {
    int i = blockIdx.x * blockDim.x + threadIdx.x;
    if (i < N_CONN * D128) {
        int r = i >> 7, c = i & 127;
        conn[i] = (c < NFEAT) ? feat[r * NFEAT + c] : 0.f;
        if (i < N_IP * D128) ip[i] = 1.f;
    }
}
__global__ void zero_rc(float* __restrict__ c1, float* __restrict__ c2) {
    int i = blockIdx.x * blockDim.x + threadIdx.x;
    if (i < N_CONN) c1[i] = 0.f;
    if (i < N_IP) c2[i] = 0.f;
}
__global__ void count2(const int* __restrict__ d1, const int* __restrict__ d2,
                       float* __restrict__ c1, float* __restrict__ c2) {
    int i = blockIdx.x * blockDim.x + threadIdx.x;
    if (i < N_E) atomicAdd(c1 + d1[i], 1.f);
    else if (i < 2 * N_E) atomicAdd(c2 + d2[i - N_E], 1.f);
}
__global__ void recip2(float* __restrict__ c1, float* __restrict__ c2) {
    int i = blockIdx.x * blockDim.x + threadIdx.x;
    if (i < N_CONN) c1[i] = 1.f / fmaxf(c1[i], 1.f);
    if (i < N_IP) c2[i] = 1.f / fmaxf(c2[i], 1.f);
}
__global__ void zero2(float* __restrict__ a, int n4a, float* __restrict__ b, int n4b) {
    int i = blockIdx.x * blockDim.x + threadIdx.x;
    if (i < n4a) *(float4*)(a + (size_t)i * 4) = make_float4(0.f, 0.f, 0.f, 0.f);
    else if (i < n4a + n4b)
        *(float4*)(b + (size_t)(i - n4a) * 4) = make_float4(0.f, 0.f, 0.f, 0.f);
}

// ---------------- merged edge message + scatter (both directions, red.v4) ----------------
__global__ void edge_msg2x(
    const int* __restrict__ s0, const int* __restrict__ d0,
    const int* __restrict__ s1, const int* __restrict__ d1,
    const float* __restrict__ XS0, const float* __restrict__ XD0,
    const float* __restrict__ XS1, const float* __restrict__ XD1,
    const float* __restrict__ b0, const float* __restrict__ b1,
    float* __restrict__ out0, float* __restrict__ out1)
{
    int gw = (blockIdx.x * blockDim.x + threadIdx.x) >> 5;
    int lane = threadIdx.x & 31;
    const int* srcp;
    const int* dstp;
    const float *XS, *XD, *bias;
    float* outp;
    if (gw < N_E) {
        srcp = s0; dstp = d0; XS = XS0; XD = XD0; bias = b0; outp = out0;
    } else {
        gw -= N_E;
        if (gw >= N_E) return;
        srcp = s1; dstp = d1; XS = XS1; XD = XD1; bias = b1; outp = out1;
    }
    int s = __ldg(srcp + gw);
    int d = __ldg(dstp + gw);
    int c = lane << 2;
    float4 a = *(const float4*)(XS + (size_t)s * 256 + c);
    float4 b = *(const float4*)(XD + (size_t)d * 256 + c);
    float4 bb = *(const float4*)(bias + c);
    float4 m;
    m.x = fmaxf(a.x + b.x + bb.x, 0.f);
    m.y = fmaxf(a.y + b.y + bb.y, 0.f);
    m.z = fmaxf(a.z + b.z + bb.z, 0.f);
    m.w = fmaxf(a.w + b.w + bb.w, 0.f);
    float* p = outp + (size_t)d * 128 + c;
    asm volatile("red.global.add.v4.f32 [%0], {%1, %2, %3, %4};"
                 :: "l"(p), "f"(m.x), "f"(m.y), "f"(m.z), "f"(m.w) : "memory");
}

// ---------------- merged GRU gate (ip + conn) + agg zero-fill tail ----------------
__device__ __forceinline__ float gru1(float xz, float hz, float xr, float hr,
                                      float xh, float hh, float h) {
    float z = 1.f / (1.f + expf(-(xz + hz)));
    float r = 1.f / (1.f + expf(-(xr + hr)));
    float c = tanhf(xh + r * hh);
    return z * h + (1.f - z) * c;
}
#define G_IP   (N_IP * 32)
#define G_ALL  ((N_IP + N_CONN) * 32)
#define Z_IP   (N_IP * 32)
#define Z_CONN (N_CONN * 32)
__global__ void gru_gate2x(float* __restrict__ h0, const float* __restrict__ xm0,
                           const float* __restrict__ hm0,
                           float* __restrict__ h1, const float* __restrict__ xm1,
                           const float* __restrict__ hm1,
                           float* __restrict__ za, float* __restrict__ zb)
{
    int idx = blockIdx.x * blockDim.x + threadIdx.x;
    if (idx >= G_ALL) {
        int z = idx - G_ALL;
        if (z < Z_IP) {
            *(float4*)(za + (size_t)z * 4) = make_float4(0.f, 0.f, 0.f, 0.f);
        } else {
            z -= Z_IP;
            if (z < Z_CONN)
                *(float4*)(zb + (size_t)z * 4) = make_float4(0.f, 0.f, 0.f, 0.f);
        }
        return;
    }
    float* h;
    const float *xm, *hm;
    if (idx < G_IP) {
        h = h0; xm = xm0; hm = hm0;
    } else {
        idx -= G_IP;
        h = h1; xm = xm1; hm = hm1;
    }
    int row = idx >> 5;
    int c = (idx & 31) << 2;
    const float* x = xm + (size_t)row * 384;
    const float* hh = hm + (size_t)row * 384;
    float4 xz = *(const float4*)(x + c);
    float4 xr = *(const float4*)(x + 128 + c);
    float4 xh = *(const float4*)(x + 256 + c);
    float4 hz = *(const float4*)(hh + c);
    float4 hr = *(const float4*)(hh + 128 + c);
    float4 hc = *(const float4*)(hh + 256 + c);
    float* hp = h + (size_t)row * 128 + c;
    float4 hv = *(const float4*)hp;
    float4 o;
    o.x = gru1(xz.x, hz.x, xr.x, hr.x, xh.x, hc.x, hv.x);
    o.y = gru1(xz.y, hz.y, xr.y, hr.y, xh.y, hc.y, hv.y);
    o.z = gru1(xz.z, hz.z, xr.z, hr.z, xh.z, hc.z, hv.z);
    o.w = gru1(xz.w, hz.w, xr.w, hr.w, xh.w, hc.w, hv.w);
    *(float4*)hp = o;
}

// ---------------- readout tail ----------------
__global__ void readout_kernel(const float* __restrict__ H2, const float* __restrict__ W3,
                               const float* __restrict__ b3, float* __restrict__ out, int M)
{
    __shared__ float w[64 * 15];
    __shared__ float bb[15];
    for (int i = threadIdx.x; i < 64 * 15; i += blockDim.x) w[i] = W3[i];
    if (threadIdx.x < 15) bb[threadIdx.x] = b3[threadIdx.x];
    __syncthreads();
    int row = blockIdx.x * blockDim.x + threadIdx.x;
    if (row >= M) return;
    float acc[15];
#pragma unroll
    for (int j = 0; j < 15; j++) acc[j] = bb[j];
    const float* hrow = H2 + (size_t)row * 64;
#pragma unroll 16
    for (int k = 0; k < 64; k++) {
        float hv = __ldg(hrow + k);
#pragma unroll
        for (int j = 0; j < 15; j++) acc[j] += hv * w[k * 15 + j];
    }
    float mx = acc[0];
#pragma unroll
    for (int j = 1; j < 15; j++) mx = fmaxf(mx, acc[j]);
    float sum = 0.f;
#pragma unroll
    for (int j = 0; j < 15; j++) { acc[j] = expf(acc[j] - mx); sum += acc[j]; }
    float inv = 1.f / sum;
    float* op = out + (size_t)row * 15;
#pragma unroll
    for (int j = 0; j < 15; j++) op[j] = acc[j] * inv;
}

// ---------------- host side ----------------
static const int SMEM_B64  = 2 * 64 * 256 + 2 * 128 * 256;   // 98304 (BM=64, NTILE=128)
static const int SMEM_R64  = 2 * 128 * 256 + 2 * 64 * 256;   // 98304 (BM=128, NTILE=64)

static inline void launch_g128(const float* A, const __nv_bfloat16* Bh, const __nv_bfloat16* Bl,
                               float* C, int M, int Ntot, int ldc, const float* bias,
                               const float* rs, int relu) {
    dim3 g((M + 63) / 64, Ntot / 128);
    mma_gemm<128, 64><<<g, 256, SMEM_B64>>>(A, Bh, Bl, C, M, ldc, bias, rs, relu);
}

extern "C" void kernel_launch(void* const* d_in, const int* in_sizes, int n_in,
                              void* d_out, int out_size)
{
    const float* feat  = (const float*)d_in[0];
    const int*   s_i2c = (const int*)d_in[1];
    const int*   d_i2c = (const int*)d_in[2];
    const int*   s_c2i = (const int*)d_in[3];
    const int*   d_c2i = (const int*)d_in[4];
    const float* W_m1  = (const float*)d_in[5];
    const float* b_m1  = (const float*)d_in[6];
    const float* W_m2  = (const float*)d_in[7];
    const float* b_m2  = (const float*)d_in[8];
    const float* gik   = (const float*)d_in[9];
    const float* gir   = (const float*)d_in[10];
    const float* gib   = (const float*)d_in[11];
    const float* gck   = (const float*)d_in[12];
    const float* gcr   = (const float*)d_in[13];
    const float* gcb   = (const float*)d_in[14];
    const float* Wr1   = (const float*)d_in[15];
    const float* br1   = (const float*)d_in[16];
    const float* Wr2   = (const float*)d_in[17];
    const float* br2   = (const float*)d_in[18];
    const float* Wr3   = (const float*)d_in[19];
    const float* br3   = (const float*)d_in[20];
    float* out = (float*)d_out;

    cudaFuncSetAttribute((void*)mma_gemm<128, 64>,
                         cudaFuncAttributeMaxDynamicSharedMemorySize, SMEM_B64);
    cudaFuncSetAttribute((void*)mma_gemm<64, 128>,
                         cudaFuncAttributeMaxDynamicSharedMemorySize, SMEM_R64);

    void* p;
    cudaGetSymbolAddress(&p, g_ip);       float* ip       = (float*)p;
    cudaGetSymbolAddress(&p, g_conn);     float* conn     = (float*)p;
    cudaGetSymbolAddress(&p, g_msg_ip);   float* msg_ip   = (float*)p;
    cudaGetSymbolAddress(&p, g_msg_conn); float* msg_conn = (float*)p;
    cudaGetSymbolAddress(&p, g_agg_conn); float* agg_conn = (float*)p;
    cudaGetSymbolAddress(&p, g_agg_ip);   float* agg_ip   = (float*)p;
    cudaGetSymbolAddress(&p, g_xm_ip);    float* xm_ip    = (float*)p;
    cudaGetSymbolAddress(&p, g_hm_ip);    float* hm_ip    = (float*)p;
    cudaGetSymbolAddress(&p, g_xm_c);     float* xm_c     = (float*)p;
    cudaGetSymbolAddress(&p, g_hm_c);     float* hm_c     = (float*)p;
    cudaGetSymbolAddress(&p, g_rc_conn);  float* rc_conn  = (float*)p;
    cudaGetSymbolAddress(&p, g_rc_ip);    float* rc_ip    = (float*)p;
    cudaGetSymbolAddress(&p, g_H1);       float* H1       = (float*)p;
    cudaGetSymbolAddress(&p, g_H2);       float* H2       = (float*)p;

    __nv_bfloat16 *ipcat_h, *ipcat_l, *conncat_h, *conncat_l;
    __nv_bfloat16 *gik_h, *gik_l, *gir_h, *gir_l, *gck_h, *gck_l, *gcr_h, *gcr_l;
    __nv_bfloat16 *wr1_h, *wr1_l, *wr2_h, *wr2_l;
    cudaGetSymbolAddress(&p, g_ipcat_h);   ipcat_h   = (__nv_bfloat16*)p;
    cudaGetSymbolAddress(&p, g_ipcat_l);   ipcat_l   = (__nv_bfloat16*)p;
    cudaGetSymbolAddress(&p, g_conncat_h); conncat_h = (__nv_bfloat16*)p;
    cudaGetSymbolAddress(&p, g_conncat_l); conncat_l = (__nv_bfloat16*)p;
    cudaGetSymbolAddress(&p, g_gik_h); gik_h = (__nv_bfloat16*)p;
    cudaGetSymbolAddress(&p, g_gik_l); gik_l = (__nv_bfloat16*)p;
    cudaGetSymbolAddress(&p, g_gir_h); gir_h = (__nv_bfloat16*)p;
    cudaGetSymbolAddress(&p, g_gir_l); gir_l = (__nv_bfloat16*)p;
    cudaGetSymbolAddress(&p, g_gck_h); gck_h = (__nv_bfloat16*)p;
    cudaGetSymbolAddress(&p, g_gck_l); gck_l = (__nv_bfloat16*)p;
    cudaGetSymbolAddress(&p, g_gcr_h); gcr_h = (__nv_bfloat16*)p;
    cudaGetSymbolAddress(&p, g_gcr_l); gcr_l = (__nv_bfloat16*)p;
    cudaGetSymbolAddress(&p, g_wr1_h); wr1_h = (__nv_bfloat16*)p;
    cudaGetSymbolAddress(&p, g_wr1_l); wr1_l = (__nv_bfloat16*)p;
    cudaGetSymbolAddress(&p, g_wr2_h); wr2_h = (__nv_bfloat16*)p;
    cudaGetSymbolAddress(&p, g_wr2_l); wr2_l = (__nv_bfloat16*)p;

    // --- merged weight prep (one launch) ---
    prep_all<<<(286720 + 255) / 256, 256>>>(W_m1, W_m2, gik, gir, gck, gcr, Wr1, Wr2);

    // --- segment counts + state init + initial agg zero ---
    zero_rc<<<(N_CONN + 255) / 256, 256>>>(rc_conn, rc_ip);
    count2<<<(2 * N_E + 255) / 256, 256>>>(d_i2c, d_c2i, rc_conn, rc_ip);
    recip2<<<(N_CONN + 255) / 256, 256>>>(rc_conn, rc_ip);
    init_states<<<(N_CONN * D128 + 255) / 256, 256>>>(ip, conn, feat);
    zero2<<<(Z_IP + Z_CONN + 255) / 256, 256>>>(agg_ip, Z_IP, agg_conn, Z_CONN);

    const int edge_blocks = (2 * N_E * 32 + 255) / 256;
    const int gate_blocks = (G_ALL + Z_IP + Z_CONN + 255) / 256;

    for (int t = 0; t < T_ITERS; t++) {
        // merged message GEMMs
        launch_g128(ip,   ipcat_h,   ipcat_l,   msg_ip,   N_IP,   256, 256, nullptr, nullptr, 0);
        launch_g128(conn, conncat_h, conncat_l, msg_conn, N_CONN, 256, 256, nullptr, nullptr, 0);

        // merged edge kernels (both directions, vectorized reductions)
        edge_msg2x<<<edge_blocks, 256>>>(s_i2c, d_i2c, s_c2i, d_c2i,
                                         msg_ip, msg_conn, msg_conn + 128, msg_ip + 128,
                                         b_m1, b_m2, agg_conn, agg_ip);

        // GRU pre-activations
        launch_g128(agg_ip,   gik_h, gik_l, xm_ip, N_IP,   384, 384, gib,       rc_ip,   0);
        launch_g128(ip,       gir_h, gir_l, hm_ip, N_IP,   384, 384, gib + 384, nullptr, 0);
        launch_g128(agg_conn, gck_h, gck_l, xm_c,  N_CONN, 384, 384, gcb,       rc_conn, 0);
        launch_g128(conn,     gcr_h, gcr_l, hm_c,  N_CONN, 384, 384, gcb + 384, nullptr, 0);

        // merged gate update (in place) + zero agg for next iteration
        gru_gate2x<<<gate_blocks, 256>>>(ip, xm_ip, hm_ip, conn, xm_c, hm_c,
                                         agg_ip, agg_conn);
    }

    // --- readout ---
    launch_g128(conn, wr1_h, wr1_l, H1, N_CONN, 128, 128, br1, nullptr, 1);
    {
        dim3 g((N_CONN + 127) / 128, 1);
        mma_gemm<64, 128><<<g, 256, SMEM_R64>>>(H1, wr2_h, wr2_l, H2, N_CONN, 64, br2,
                                                nullptr, 1);
    }
    readout_kernel<<<(N_CONN + 127) / 128, 128>>>(H2, Wr3, br3, out, N_CONN);
}